// round 7
// baseline (speedup 1.0000x reference)
#include <cuda_runtime.h>
#include <math.h>

// Problem constants
#define Bsz   2048
#define Hh    512
#define DIN   128
#define TT    96
#define DOUT  64
#define G3    1536   // 3*H

typedef unsigned long long u64;

// ---------------------------------------------------------------------------
// Weight scratch (transposed K-major layouts), module-static device memory.
// ---------------------------------------------------------------------------
__device__ __align__(16) float g_Wih0_t[DIN * G3];   // [k=128][n=1536]
__device__ __align__(16) float g_Whh0_t[Hh  * G3];   // [k=512][n=1536]
__device__ __align__(16) float g_Wih1_t[Hh  * G3];   // [k=512][n=1536]
__device__ __align__(16) float g_Whh1_t[Hh  * G3];   // [k=512][n=1536]
__device__ __align__(16) float g_Wfc_t [Hh  * DIN];  // [k=512][o=128]
__device__ __align__(16) float g_Wpj_t [DIN * DOUT]; // [d=128][o=64]

// ---------------------------------------------------------------------------
// Reorg: transpose all weight matrices into K-major scratch.
// ---------------------------------------------------------------------------
__global__ void reorg_kernel(const float* __restrict__ Wih0,
                             const float* __restrict__ Whh0,
                             const float* __restrict__ Wih1,
                             const float* __restrict__ Whh1,
                             const float* __restrict__ Wfc,
                             const float* __restrict__ Wpj)
{
    int idx = blockIdx.x * blockDim.x + threadIdx.x;
    const int n0 = DIN * G3;     // 196608
    const int n1 = Hh * G3;      // 786432
    const int n4 = Hh * DIN;     // 65536
    const int n5 = DIN * DOUT;   // 8192

    if (idx < n0) {
        int k = idx / G3, n = idx - k * G3;
        g_Wih0_t[idx] = Wih0[n * DIN + k];
        return;
    }
    idx -= n0;
    if (idx < n1) {
        int k = idx / G3, n = idx - k * G3;
        g_Whh0_t[idx] = Whh0[n * Hh + k];
        return;
    }
    idx -= n1;
    if (idx < n1) {
        int k = idx / G3, n = idx - k * G3;
        g_Wih1_t[idx] = Wih1[n * Hh + k];
        return;
    }
    idx -= n1;
    if (idx < n1) {
        int k = idx / G3, n = idx - k * G3;
        g_Whh1_t[idx] = Whh1[n * Hh + k];
        return;
    }
    idx -= n1;
    if (idx < n4) {
        int k = idx / DIN, n = idx - k * DIN;   // n = output index o
        g_Wfc_t[idx] = Wfc[n * Hh + k];
        return;
    }
    idx -= n4;
    if (idx < n5) {
        int k = idx / DOUT, n = idx - k * DOUT; // n = output index o
        g_Wpj_t[idx] = Wpj[n * DIN + k];
    }
}

// ---------------------------------------------------------------------------
// Packed dual-fp32 helpers (FFMA2 via PTX f32x2).
// ---------------------------------------------------------------------------
union F4 { float4 v; float f[4]; u64 d[2]; };
union F2 { float2 v; float f[2]; u64 d; };

__device__ __forceinline__ void ffma2(u64& acc, u64 a, u64 b) {
    asm("fma.rn.f32x2 %0, %1, %2, %0;" : "+l"(acc) : "l"(a), "l"(b));
}
__device__ __forceinline__ u64 pack2(float x) {
    u64 r;
    asm("mov.b64 %0, {%1, %1};" : "=l"(r) : "f"(x));
    return r;
}
__device__ __forceinline__ float2 unpack2(u64 p) {
    float lo, hi;
    asm("mov.b64 {%0, %1}, %2;" : "=f"(lo), "=f"(hi) : "l"(p));
    return make_float2(lo, hi);
}

__device__ __forceinline__ float sigf(float x) {
    return __fdividef(1.0f, 1.0f + __expf(-x));
}
__device__ __forceinline__ float tanh_f(float x) {
    return __fdividef(2.0f, 1.0f + __expf(-2.0f * x)) - 1.0f;
}

#define NB 8   // batches per thread

// ---------------------------------------------------------------------------
// One GRU layer for 16 batch rows held in smem.
// 512 threads: tx in [0,256) = one float2 (f32x2 pair) column per gate,
//              ty in {0,1}   = 8-batch group.
// Weight redundancy 2x (same L1 bytes as R4) but 16 warps/SM and only
// ~64 accumulator regs/thread -> 4 warps/SMSP of latency hiding.
// Weights load directly as u64 f32x2 pairs (no repacking).
// ---------------------------------------------------------------------------
template <int DX>
__device__ __forceinline__ void gru_layer(const float* __restrict__ sx,
                                          const float* __restrict__ hc,
                                          float* __restrict__ hn,
                                          const float* __restrict__ Wih_t,
                                          const float* __restrict__ Whh_t,
                                          const float* __restrict__ b_ih,
                                          const float* __restrict__ b_hh,
                                          int tx, int ty)
{
    const int b0 = NB * ty;
    const int j0 = 2 * tx;        // scalar h-index base (2 per thread)
    const u64* __restrict__ Wih2 = (const u64*)(Wih_t) + tx;  // f32x2 view
    const u64* __restrict__ Whh2 = (const u64*)(Whh_t) + tx;
    // row stride in u64 units: 1536/2 = 768 ; gate stride: 512/2 = 256

    u64 aR[NB], aZ[NB], aIN[NB], aHN[NB];
#pragma unroll
    for (int i = 0; i < NB; ++i) {
        aR[i] = 0ull; aZ[i] = 0ull; aIN[i] = 0ull; aHN[i] = 0ull;
    }

    // ---- pass 1: input GEMM (accumulate r, z, i_n) ---------------------
#pragma unroll 1
    for (int k = 0; k < DX; k += 4) {
        F4 xv[NB];
#pragma unroll
        for (int i = 0; i < NB; ++i)
            xv[i].v = *(const float4*)&sx[(b0 + i) * DX + k];
#pragma unroll
        for (int kk = 0; kk < 4; ++kk) {
            const u64 wr = __ldg(&Wih2[(k + kk) * 768]);
            const u64 wz = __ldg(&Wih2[(k + kk) * 768 + 256]);
            const u64 wn = __ldg(&Wih2[(k + kk) * 768 + 512]);
#pragma unroll
            for (int i = 0; i < NB; ++i) {
                const u64 xs2 = pack2(xv[i].f[kk]);
                ffma2(aR[i],  xs2, wr);
                ffma2(aZ[i],  xs2, wz);
                ffma2(aIN[i], xs2, wn);
            }
        }
    }

    // ---- pass 2: hidden GEMM (accumulate r, z, h_n) --------------------
#pragma unroll 1
    for (int k = 0; k < Hh; k += 4) {
        F4 hv[NB];
#pragma unroll
        for (int i = 0; i < NB; ++i)
            hv[i].v = *(const float4*)&hc[(b0 + i) * Hh + k];
#pragma unroll
        for (int kk = 0; kk < 4; ++kk) {
            const u64 wr = __ldg(&Whh2[(k + kk) * 768]);
            const u64 wz = __ldg(&Whh2[(k + kk) * 768 + 256]);
            const u64 wn = __ldg(&Whh2[(k + kk) * 768 + 512]);
#pragma unroll
            for (int i = 0; i < NB; ++i) {
                const u64 hs2 = pack2(hv[i].f[kk]);
                ffma2(aR[i],  hs2, wr);
                ffma2(aZ[i],  hs2, wz);
                ffma2(aHN[i], hs2, wn);
            }
        }
    }

    // ---- gate math + write h_new ----------------------------------------
    F2 bir, bhr, biz, bhz, bin, bhn;
    bir.v = *(const float2*)(b_ih + j0);
    bhr.v = *(const float2*)(b_hh + j0);
    biz.v = *(const float2*)(b_ih + 512 + j0);
    bhz.v = *(const float2*)(b_hh + 512 + j0);
    bin.v = *(const float2*)(b_ih + 1024 + j0);
    bhn.v = *(const float2*)(b_hh + 1024 + j0);

#pragma unroll
    for (int i = 0; i < NB; ++i) {
        F2 hold, hnew;
        hold.v = *(const float2*)&hc[(b0 + i) * Hh + j0];
        const float2 r2  = unpack2(aR[i]);
        const float2 z2  = unpack2(aZ[i]);
        const float2 in2 = unpack2(aIN[i]);
        const float2 hn2 = unpack2(aHN[i]);
        const float rv[2]  = { r2.x,  r2.y  };
        const float zv[2]  = { z2.x,  z2.y  };
        const float inv[2] = { in2.x, in2.y };
        const float hnv[2] = { hn2.x, hn2.y };
#pragma unroll
        for (int q = 0; q < 2; ++q) {
            const float r = sigf(rv[q] + bir.f[q] + bhr.f[q]);
            const float z = sigf(zv[q] + biz.f[q] + bhz.f[q]);
            const float nn = tanh_f(inv[q] + bin.f[q]
                                    + r * (hnv[q] + bhn.f[q]));
            hnew.f[q] = nn + z * (hold.f[q] - nn);   // (1-z)n + z h
        }
        *(float2*)&hn[(b0 + i) * Hh + j0] = hnew.v;
    }
}

// ---------------------------------------------------------------------------
// Main persistent kernel: 128 blocks x 16 batch rows x 512 threads, T=96.
// smem: h0 double-buffer (2x16x512) + h1 double-buffer + x (16x128) = 136KB.
// ---------------------------------------------------------------------------
__global__ void __launch_bounds__(512, 1)
gru_main(const float* __restrict__ x,
         const float* __restrict__ b_ih0, const float* __restrict__ b_hh0,
         const float* __restrict__ b_ih1, const float* __restrict__ b_hh1,
         const float* __restrict__ b_fc,  const float* __restrict__ b_pj,
         float* __restrict__ y)
{
    extern __shared__ float sm[];
    float* h0A = sm;                 // 16*512
    float* h0B = sm + 8192;
    float* h1A = sm + 16384;
    float* h1B = sm + 24576;
    float* sx  = sm + 32768;         // 16*128

    const int tid = threadIdx.x;
    const int tx = tid & 255;        // 256 f32x2 columns per gate
    const int ty = tid >> 8;         // 2 batch groups of 8
    const int gb0 = blockIdx.x * 16;

    // init: zero hidden states, load x[:,0,:]
    for (int i = tid; i < 8192; i += 512) { h0A[i] = 0.f; h1A[i] = 0.f; }
    for (int i = tid; i < 2048; i += 512) { sx[i] = x[gb0 * DIN + i]; }
    __syncthreads();

    float* h0c = h0A; float* h0n = h0B;
    float* h1c = h1A; float* h1n = h1B;

    for (int t = 0; t < TT; ++t) {
        // layer 0: sx (DX=128) -> h0n
        gru_layer<DIN>(sx, h0c, h0n, g_Wih0_t, g_Whh0_t, b_ih0, b_hh0, tx, ty);
        __syncthreads();

        // layer 1: h0n (DX=512) -> h1n
        gru_layer<Hh>(h0n, h1c, h1n, g_Wih1_t, g_Whh1_t, b_ih1, b_hh1, tx, ty);
        __syncthreads();

        // fc: out = h1n @ Wfc^T + b_fc  -> sx (next step input)
        // 512 threads: 16 batches x 32 f4-columns (128 outputs)
        {
            const int ox = tid & 31;      // 4*ox = output col base
            const int bb = tid >> 5;      // batch 0..15
            u64 acc0 = 0ull, acc1 = 0ull;

            const float4* __restrict__ W4 = (const float4*)g_Wfc_t; // [512][32]
#pragma unroll 2
            for (int k = 0; k < Hh; k += 4) {
                F4 hv;
                hv.v = *(const float4*)&h1n[bb * Hh + k];
#pragma unroll
                for (int kk = 0; kk < 4; ++kk) {
                    F4 w; w.v = __ldg(&W4[(k + kk) * 32 + ox]);
                    const u64 hp = pack2(hv.f[kk]);
                    ffma2(acc0, hp, w.d[0]);
                    ffma2(acc1, hp, w.d[1]);
                }
            }
            F4 bf; bf.v = __ldg(((const float4*)b_fc) + ox);
            F4 o;
            const float2 a0 = unpack2(acc0);
            const float2 a1 = unpack2(acc1);
            o.f[0] = a0.x + bf.f[0];
            o.f[1] = a0.y + bf.f[1];
            o.f[2] = a1.x + bf.f[2];
            o.f[3] = a1.y + bf.f[3];
            // safe to overwrite sx: all threads passed the post-layer1 sync
            *(float4*)&sx[bb * DIN + 4 * ox] = o.v;
        }
        __syncthreads();

        // projection: y[b][o][t] = sx[b] . Wpj_t[:,o] + b_pj[o]
        // 256 active threads: 16 batches x 16 f4-columns (64 outputs)
        if (tid < 256) {
            const int bb = tid >> 4;      // 0..15
            const int ox = tid & 15;      // 4*ox = output col base
            F4 acc; acc.v = __ldg(((const float4*)b_pj) + ox);
            const float4* __restrict__ W4 = (const float4*)g_Wpj_t; // [128][16]
#pragma unroll 2
            for (int d = 0; d < DIN; d += 4) {
                F4 xv; xv.v = *(const float4*)&sx[bb * DIN + d];
#pragma unroll
                for (int kk = 0; kk < 4; ++kk) {
                    F4 w; w.v = __ldg(&W4[(d + kk) * 16 + ox]);
#pragma unroll
                    for (int l = 0; l < 4; ++l)
                        acc.f[l] = fmaf(xv.f[kk], w.f[l], acc.f[l]);
                }
            }
            const size_t base = ((size_t)(gb0 + bb) * DOUT + 4 * ox) * TT + t;
            y[base]          = acc.f[0];
            y[base + TT]     = acc.f[1];
            y[base + 2 * TT] = acc.f[2];
            y[base + 3 * TT] = acc.f[3];
        }

        // swap double buffers
        float* tp;
        tp = h0c; h0c = h0n; h0n = tp;
        tp = h1c; h1c = h1n; h1n = tp;
    }
}

// ---------------------------------------------------------------------------
// Entry point
// ---------------------------------------------------------------------------
extern "C" void kernel_launch(void* const* d_in, const int* in_sizes, int n_in,
                              void* d_out, int out_size)
{
    (void)in_sizes; (void)n_in; (void)out_size;

    const float* x     = (const float*)d_in[0];
    const float* Wih0  = (const float*)d_in[1];
    const float* Whh0  = (const float*)d_in[2];
    const float* bih0  = (const float*)d_in[3];
    const float* bhh0  = (const float*)d_in[4];
    const float* Wih1  = (const float*)d_in[5];
    const float* Whh1  = (const float*)d_in[6];
    const float* bih1  = (const float*)d_in[7];
    const float* bhh1  = (const float*)d_in[8];
    const float* Wfc   = (const float*)d_in[9];
    const float* bfc   = (const float*)d_in[10];
    const float* Wpj   = (const float*)d_in[11];
    const float* bpj   = (const float*)d_in[12];
    float* y = (float*)d_out;

    const int smem_bytes = (4 * 16 * Hh + 16 * DIN) * (int)sizeof(float); // 139264
    cudaFuncSetAttribute(gru_main,
                         cudaFuncAttributeMaxDynamicSharedMemorySize,
                         smem_bytes);

    reorg_kernel<<<2629632 / 256, 256>>>(Wih0, Whh0, Wih1, Whh1, Wfc, Wpj);

    gru_main<<<128, 512, smem_bytes>>>(x, bih0, bhh0, bih1, bhh1, bfc, bpj, y);
}

// round 10
// speedup vs baseline: 1.5373x; 1.5373x over previous
#include <cuda_runtime.h>
#include <cuda_bf16.h>
#include <math.h>

// Problem constants
#define Bsz   2048
#define Hh    512
#define DIN   128
#define TT    96
#define DOUT  64

typedef unsigned long long u64;
typedef unsigned int u32;

// ---------------------------------------------------------------------------
// Device-global state & weight scratch
// ---------------------------------------------------------------------------
__device__ __align__(16) float g_h0a[Bsz * Hh];
__device__ __align__(16) float g_h0b[Bsz * Hh];
__device__ __align__(16) float g_h1a[Bsz * Hh];
__device__ __align__(16) float g_h1b[Bsz * Hh];
__device__ __align__(16) float g_xfc[Bsz * DIN];

__device__ __align__(16) float g_Wfc_t[Hh * DIN];   // [k=512][o=128]
__device__ __align__(16) float g_Wpj_t[DIN * DOUT]; // [d=128][o=64]

// Split bf16 GRU weights, augmented K layout: [gate(3)][n(512)][k(KTOT)]
// layer0 KTOT = 128+512 = 640 ; layer1 KTOT = 512+512 = 1024
#define K0TOT 640
#define K1TOT 1024
__device__ __align__(16) __nv_bfloat16 g_W0hi[3 * 512 * K0TOT];
__device__ __align__(16) __nv_bfloat16 g_W0lo[3 * 512 * K0TOT];
__device__ __align__(16) __nv_bfloat16 g_W1hi[3 * 512 * K1TOT];
__device__ __align__(16) __nv_bfloat16 g_W1lo[3 * 512 * K1TOT];

// ---------------------------------------------------------------------------
// Helpers
// ---------------------------------------------------------------------------
union F4 { float4 v; float f[4]; u64 d[2]; };

__device__ __forceinline__ void ffma2(u64& acc, u64 a, u64 b) {
    asm("fma.rn.f32x2 %0, %1, %2, %0;" : "+l"(acc) : "l"(a), "l"(b));
}
__device__ __forceinline__ u64 pack2(float x) {
    u64 r; asm("mov.b64 %0, {%1, %1};" : "=l"(r) : "f"(x)); return r;
}
__device__ __forceinline__ float2 unpack2(u64 p) {
    float lo, hi; asm("mov.b64 {%0, %1}, %2;" : "=f"(lo), "=f"(hi) : "l"(p));
    return make_float2(lo, hi);
}
__device__ __forceinline__ float sigf(float x) {
    return __fdividef(1.0f, 1.0f + __expf(-x));
}
__device__ __forceinline__ float tanh_f(float x) {
    return __fdividef(2.0f, 1.0f + __expf(-2.0f * x)) - 1.0f;
}
__device__ __forceinline__ u32 bfpack(float a, float b) {
    __nv_bfloat162 t = __floats2bfloat162_rn(a, b);
    return *(u32*)&t;
}

// m16n8k16 row.col bf16 MMA, fp32 accumulate (sm_80+ baseline ISA)
__device__ __forceinline__ void mma_bf16(float* d, const u32* a, u32 b0, u32 b1) {
    asm volatile(
        "mma.sync.aligned.m16n8k16.row.col.f32.bf16.bf16.f32 "
        "{%0,%1,%2,%3}, {%4,%5,%6,%7}, {%8,%9}, {%0,%1,%2,%3};\n"
        : "+f"(d[0]), "+f"(d[1]), "+f"(d[2]), "+f"(d[3])
        : "r"(a[0]), "r"(a[1]), "r"(a[2]), "r"(a[3]), "r"(b0), "r"(b1));
}

// ---------------------------------------------------------------------------
// Reorg 1: split GRU weights into bf16 hi/lo, augmented-K K-major layout.
// ---------------------------------------------------------------------------
__global__ void pack_weights(const float* __restrict__ Wih0,
                             const float* __restrict__ Whh0,
                             const float* __restrict__ Wih1,
                             const float* __restrict__ Whh1)
{
    int idx = blockIdx.x * blockDim.x + threadIdx.x;
    const int n0 = 3 * 512 * K0TOT;
    const int n1 = 3 * 512 * K1TOT;

    const float *Wih, *Whh;
    int KTOT, XK;
    __nv_bfloat16 *dhi, *dlo;
    if (idx < n0) {
        Wih = Wih0; Whh = Whh0; KTOT = K0TOT; XK = DIN;
        dhi = g_W0hi; dlo = g_W0lo;
    } else {
        idx -= n0;
        if (idx >= n1) return;
        Wih = Wih1; Whh = Whh1; KTOT = K1TOT; XK = 512;
        dhi = g_W1hi; dlo = g_W1lo;
    }

    int k = idx % KTOT;
    int row = idx / KTOT;          // gate*512 + n  (matches Wih/Whh row index)
    float v = (k < XK) ? Wih[row * XK + k] : Whh[row * 512 + (k - XK)];
    __nv_bfloat16 hi = __float2bfloat16_rn(v);
    dhi[idx] = hi;
    dlo[idx] = __float2bfloat16_rn(v - __bfloat162float(hi));
}

// ---------------------------------------------------------------------------
// Reorg 2: fc/proj transposes + state init
// ---------------------------------------------------------------------------
__global__ void reorg_fc_init(const float* __restrict__ Wfc,
                              const float* __restrict__ Wpj,
                              const float* __restrict__ x)
{
    int idx = blockIdx.x * blockDim.x + threadIdx.x;
    if (idx < Hh * DIN) {
        int k = idx / DIN, n = idx - k * DIN;
        g_Wfc_t[idx] = Wfc[n * Hh + k];
        return;
    }
    idx -= Hh * DIN;
    if (idx < DIN * DOUT) {
        int k = idx / DOUT, n = idx - k * DOUT;
        g_Wpj_t[idx] = Wpj[n * DIN + k];
        return;
    }
    idx -= DIN * DOUT;
    if (idx < Bsz * Hh) {
        g_h0a[idx] = 0.f; g_h1a[idx] = 0.f;
        return;
    }
    idx -= Bsz * Hh;
    if (idx < Bsz * DIN) {
        g_xfc[idx] = x[idx];   // x is [B, 1, 128]
    }
}

// ---------------------------------------------------------------------------
// Warp-MMA GRU layer step.
// Grid 256: mt = bx>>4 (128-batch tile), hc = bx&15 (32 h-cols).
// CTA: 256 threads = 8 warps, warp grid 4(M) x 2(HC): warp tile 32 x 16.
// Planes: 0=r, 1=z, 2=n_ih (x-chunks), 3=n_hh (h-chunks).
// K loop: chunks of 64 over augmented K = [x | h].
// 3-term bf16 split: AhiBhi + AhiBlo + AloBhi.
// smem: A hi/lo [128][72]bf16, B hi/lo [96][72]bf16  (stride 72 = no conflicts)
// ---------------------------------------------------------------------------
#define A_HI 0
#define A_LO 18432
#define B_HI 36864
#define B_LO 50688
#define SM_TOTAL 64512

template <int KTOT, int XK, int XSTR>
__global__ void __launch_bounds__(256, 1)
gru_layer_mma(const float* __restrict__ xsrc,
              const float* __restrict__ hin,
              float* __restrict__ hout,
              const __nv_bfloat16* __restrict__ Whi,
              const __nv_bfloat16* __restrict__ Wlo,
              const float* __restrict__ b_ih,
              const float* __restrict__ b_hh)
{
    extern __shared__ char smem[];
    u32* AHI = (u32*)(smem + A_HI);
    u32* ALO = (u32*)(smem + A_LO);
    u32* BHI = (u32*)(smem + B_HI);
    u32* BLO = (u32*)(smem + B_LO);

    const int tid = threadIdx.x;
    const int wid = tid >> 5;
    const int lane = tid & 31;
    const int g_ = lane >> 2;     // 0..7
    const int q_ = lane & 3;      // 0..3
    const int wm = wid & 3;       // M warp (4 x 32 rows)
    const int wn = wid >> 2;      // HC warp (2 x 16 cols)
    const int mt = blockIdx.x >> 4;
    const int hc = blockIdx.x & 15;
    const int m0 = mt * 128;
    const int hc0 = hc * 32;

    float acc[4][2][2][4];        // [plane][mtile][ntile][dreg]
#pragma unroll
    for (int p = 0; p < 4; ++p)
#pragma unroll
        for (int a = 0; a < 2; ++a)
#pragma unroll
            for (int b = 0; b < 2; ++b)
#pragma unroll
                for (int c = 0; c < 4; ++c) acc[p][a][b][c] = 0.f;

    const int CH = KTOT / 64;
    const int XCH = XK / 64;

#pragma unroll 1
    for (int c = 0; c < CH; ++c) {
        const bool is_x = (c < XCH);
        const float* asrc = is_x ? xsrc : hin;
        const int stride = is_x ? XSTR : 512;
        const int col0 = is_x ? c * 64 : (c - XCH) * 64;

        // ---- A fill: 128 rows x 64 k, fp32 -> bf16 hi/lo -----------------
        for (int e = tid; e < 128 * 16; e += 256) {
            const int m = e >> 4, qq = e & 15;
            F4 v;
            v.v = *(const float4*)&asrc[(m0 + m) * stride + col0 + 4 * qq];
            __nv_bfloat16 h0 = __float2bfloat16_rn(v.f[0]);
            __nv_bfloat16 h1 = __float2bfloat16_rn(v.f[1]);
            __nv_bfloat16 h2 = __float2bfloat16_rn(v.f[2]);
            __nv_bfloat16 h3 = __float2bfloat16_rn(v.f[3]);
            u32 hiA = bfpack(v.f[0], v.f[1]);
            u32 hiB = bfpack(v.f[2], v.f[3]);
            u32 loA = bfpack(v.f[0] - __bfloat162float(h0),
                             v.f[1] - __bfloat162float(h1));
            u32 loB = bfpack(v.f[2] - __bfloat162float(h2),
                             v.f[3] - __bfloat162float(h3));
            const int o = m * 36 + 2 * qq;
            AHI[o] = hiA; AHI[o + 1] = hiB;
            ALO[o] = loA; ALO[o + 1] = loB;
        }

        // ---- B fill: 3 gates x 32 n x 64 k, pre-split copies -------------
        for (int e = tid; e < 96 * 8; e += 256) {
            const int brow = e >> 3, q = e & 7;
            const int gate = brow >> 5, n = brow & 31;
            const long src = (long)(gate * 512 + hc0 + n) * KTOT + c * 64;
            const float4 vh = ((const float4*)Whi)[src / 8 + q];
            const float4 vl = ((const float4*)Wlo)[src / 8 + q];
            ((float4*)(smem + B_HI))[brow * 9 + q] = vh;
            ((float4*)(smem + B_LO))[brow * 9 + q] = vl;
        }
        __syncthreads();

        // ---- MMA: 4 k-steps of 16 ---------------------------------------
        const int nplane = is_x ? 2 : 3;
#pragma unroll
        for (int ks = 0; ks < 4; ++ks) {
            const int k0 = ks * 8 + q_;   // u32 units within row
            u32 a_hi[2][4], a_lo[2][4];
#pragma unroll
            for (int mtl = 0; mtl < 2; ++mtl) {
                const int r0 = wm * 32 + mtl * 16 + g_;
                a_hi[mtl][0] = AHI[r0 * 36 + k0];
                a_hi[mtl][1] = AHI[(r0 + 8) * 36 + k0];
                a_hi[mtl][2] = AHI[r0 * 36 + k0 + 4];
                a_hi[mtl][3] = AHI[(r0 + 8) * 36 + k0 + 4];
                a_lo[mtl][0] = ALO[r0 * 36 + k0];
                a_lo[mtl][1] = ALO[(r0 + 8) * 36 + k0];
                a_lo[mtl][2] = ALO[r0 * 36 + k0 + 4];
                a_lo[mtl][3] = ALO[(r0 + 8) * 36 + k0 + 4];
            }
#pragma unroll
            for (int pl = 0; pl < 3; ++pl) {
                const int gate = (pl == 2) ? 2 : pl;
                const int ai = (pl == 2) ? nplane : pl;
#pragma unroll
                for (int nt = 0; nt < 2; ++nt) {
                    const int br = gate * 32 + wn * 16 + nt * 8 + g_;
                    const u32 bh0 = BHI[br * 36 + k0];
                    const u32 bh1 = BHI[br * 36 + k0 + 4];
                    const u32 bl0 = BLO[br * 36 + k0];
                    const u32 bl1 = BLO[br * 36 + k0 + 4];
#pragma unroll
                    for (int mtl = 0; mtl < 2; ++mtl) {
                        mma_bf16(acc[ai][mtl][nt], a_hi[mtl], bh0, bh1);
                        mma_bf16(acc[ai][mtl][nt], a_hi[mtl], bl0, bl1);
                        mma_bf16(acc[ai][mtl][nt], a_lo[mtl], bh0, bh1);
                    }
                }
            }
        }
        __syncthreads();
    }

    // ---- epilogue: gate math + h write ----------------------------------
#pragma unroll
    for (int nt = 0; nt < 2; ++nt) {
        const int j = hc0 + wn * 16 + nt * 8 + 2 * q_;
        const float2 bir = *(const float2*)&b_ih[j];
        const float2 bhr = *(const float2*)&b_hh[j];
        const float2 biz = *(const float2*)&b_ih[512 + j];
        const float2 bhz = *(const float2*)&b_hh[512 + j];
        const float2 bin = *(const float2*)&b_ih[1024 + j];
        const float2 bhn = *(const float2*)&b_hh[1024 + j];
        const float brx = bir.x + bhr.x, bry = bir.y + bhr.y;
        const float bzx = biz.x + bhz.x, bzy = biz.y + bhz.y;
#pragma unroll
        for (int mtl = 0; mtl < 2; ++mtl) {
            const int ra = m0 + wm * 32 + mtl * 16 + g_;
#pragma unroll
            for (int rr = 0; rr < 2; ++rr) {
                const int row = ra + rr * 8;
                const float2 hold = *(const float2*)&hin[row * 512 + j];
                const float aRx = acc[0][mtl][nt][2 * rr];
                const float aRy = acc[0][mtl][nt][2 * rr + 1];
                const float aZx = acc[1][mtl][nt][2 * rr];
                const float aZy = acc[1][mtl][nt][2 * rr + 1];
                const float aIx = acc[2][mtl][nt][2 * rr];
                const float aIy = acc[2][mtl][nt][2 * rr + 1];
                const float aHx = acc[3][mtl][nt][2 * rr];
                const float aHy = acc[3][mtl][nt][2 * rr + 1];

                const float r0 = sigf(aRx + brx);
                const float r1 = sigf(aRy + bry);
                const float z0 = sigf(aZx + bzx);
                const float z1 = sigf(aZy + bzy);
                const float n0 = tanh_f(aIx + bin.x + r0 * (aHx + bhn.x));
                const float n1 = tanh_f(aIy + bin.y + r1 * (aHy + bhn.y));
                float2 o;
                o.x = n0 + z0 * (hold.x - n0);
                o.y = n1 + z1 * (hold.y - n1);
                *(float2*)&hout[row * 512 + j] = o;
            }
        }
    }
}

// ---------------------------------------------------------------------------
// fc + projection (fp32 / FFMA2), one launch per step. grid 128 x 16 batches.
// ---------------------------------------------------------------------------
__global__ void __launch_bounds__(256, 1)
fc_proj(const float* __restrict__ h1,
        const float* __restrict__ b_fc, const float* __restrict__ b_pj,
        float* __restrict__ xfc, float* __restrict__ y, int t)
{
    __shared__ float sh1[16 * 512];
    __shared__ float sx[16 * 128];
    const int tid = threadIdx.x;
    const int gb0 = blockIdx.x * 16;

    for (int i = tid; i < 8192; i += 256) sh1[i] = h1[gb0 * 512 + i];
    __syncthreads();

    {
        const int ox = tid & 31;
        const int bb = 2 * (tid >> 5);
        u64 acc[2][2] = {{0ull, 0ull}, {0ull, 0ull}};
        const float4* __restrict__ W4 = (const float4*)g_Wfc_t; // [512][32]
#pragma unroll 2
        for (int k = 0; k < Hh; k += 4) {
            F4 hv0, hv1;
            hv0.v = *(const float4*)&sh1[bb * Hh + k];
            hv1.v = *(const float4*)&sh1[(bb + 1) * Hh + k];
#pragma unroll
            for (int kk = 0; kk < 4; ++kk) {
                F4 w; w.v = __ldg(&W4[(k + kk) * 32 + ox]);
                const u64 h0p = pack2(hv0.f[kk]);
                const u64 h1p = pack2(hv1.f[kk]);
                ffma2(acc[0][0], h0p, w.d[0]);
                ffma2(acc[0][1], h0p, w.d[1]);
                ffma2(acc[1][0], h1p, w.d[0]);
                ffma2(acc[1][1], h1p, w.d[1]);
            }
        }
        F4 bf; bf.v = __ldg(((const float4*)b_fc) + ox);
        F4 o0, o1;
#pragma unroll
        for (int p = 0; p < 2; ++p) {
            const float2 a0 = unpack2(acc[0][p]);
            const float2 a1 = unpack2(acc[1][p]);
            o0.f[2 * p] = a0.x + bf.f[2 * p];
            o0.f[2 * p + 1] = a0.y + bf.f[2 * p + 1];
            o1.f[2 * p] = a1.x + bf.f[2 * p];
            o1.f[2 * p + 1] = a1.y + bf.f[2 * p + 1];
        }
        *(float4*)&sx[bb * DIN + 4 * ox]       = o0.v;
        *(float4*)&sx[(bb + 1) * DIN + 4 * ox] = o1.v;
    }
    __syncthreads();

    {
        const int bb = tid >> 4;
        const int ox = tid & 15;
        F4 acc; acc.v = __ldg(((const float4*)b_pj) + ox);
        const float4* __restrict__ W4 = (const float4*)g_Wpj_t; // [128][16]
#pragma unroll 2
        for (int d = 0; d < DIN; d += 4) {
            F4 xv; xv.v = *(const float4*)&sx[bb * DIN + d];
#pragma unroll
            for (int kk = 0; kk < 4; ++kk) {
                F4 w; w.v = __ldg(&W4[(d + kk) * 16 + ox]);
#pragma unroll
                for (int l = 0; l < 4; ++l)
                    acc.f[l] = fmaf(xv.f[kk], w.f[l], acc.f[l]);
            }
        }
        const size_t base = ((size_t)(gb0 + bb) * DOUT + 4 * ox) * TT + t;
        y[base]          = acc.f[0];
        y[base + TT]     = acc.f[1];
        y[base + 2 * TT] = acc.f[2];
        y[base + 3 * TT] = acc.f[3];
    }
    for (int i = tid; i < 2048; i += 256) xfc[gb0 * DIN + i] = sx[i];
}

// ---------------------------------------------------------------------------
// Entry point: 2 reorg + 96 x (layer0, layer1, fc_proj)
// ---------------------------------------------------------------------------
extern "C" void kernel_launch(void* const* d_in, const int* in_sizes, int n_in,
                              void* d_out, int out_size)
{
    (void)in_sizes; (void)n_in; (void)out_size;

    const float* x    = (const float*)d_in[0];
    const float* Wih0 = (const float*)d_in[1];
    const float* Whh0 = (const float*)d_in[2];
    const float* bih0 = (const float*)d_in[3];
    const float* bhh0 = (const float*)d_in[4];
    const float* Wih1 = (const float*)d_in[5];
    const float* Whh1 = (const float*)d_in[6];
    const float* bih1 = (const float*)d_in[7];
    const float* bhh1 = (const float*)d_in[8];
    const float* Wfc  = (const float*)d_in[9];
    const float* bfc  = (const float*)d_in[10];
    const float* Wpj  = (const float*)d_in[11];
    const float* bpj  = (const float*)d_in[12];
    float* y = (float*)d_out;

    float *h0a, *h0b, *h1a, *h1b, *xf;
    __nv_bfloat16 *W0hi, *W0lo, *W1hi, *W1lo;
    cudaGetSymbolAddress((void**)&h0a, g_h0a);
    cudaGetSymbolAddress((void**)&h0b, g_h0b);
    cudaGetSymbolAddress((void**)&h1a, g_h1a);
    cudaGetSymbolAddress((void**)&h1b, g_h1b);
    cudaGetSymbolAddress((void**)&xf,  g_xfc);
    cudaGetSymbolAddress((void**)&W0hi, g_W0hi);
    cudaGetSymbolAddress((void**)&W0lo, g_W0lo);
    cudaGetSymbolAddress((void**)&W1hi, g_W1hi);
    cudaGetSymbolAddress((void**)&W1lo, g_W1lo);

    cudaFuncSetAttribute(gru_layer_mma<K0TOT, DIN, DIN>,
                         cudaFuncAttributeMaxDynamicSharedMemorySize, SM_TOTAL);
    cudaFuncSetAttribute(gru_layer_mma<K1TOT, 512, 512>,
                         cudaFuncAttributeMaxDynamicSharedMemorySize, SM_TOTAL);

    {
        const int total = 3 * 512 * K0TOT + 3 * 512 * K1TOT;
        pack_weights<<<(total + 255) / 256, 256>>>(Wih0, Whh0, Wih1, Whh1);
    }
    {
        const int total = Hh * DIN + DIN * DOUT + Bsz * Hh + Bsz * DIN;
        reorg_fc_init<<<(total + 255) / 256, 256>>>(Wfc, Wpj, x);
    }

    for (int t = 0; t < TT; ++t) {
        const int ping = t & 1;
        const float* h0in = ping ? h0b : h0a;
        float*       h0out = ping ? h0a : h0b;
        const float* h1in = ping ? h1b : h1a;
        float*       h1out = ping ? h1a : h1b;

        gru_layer_mma<K0TOT, DIN, DIN><<<256, 256, SM_TOTAL>>>(
            xf, h0in, h0out, W0hi, W0lo, bih0, bhh0);
        gru_layer_mma<K1TOT, 512, 512><<<256, 256, SM_TOTAL>>>(
            h0out, h1in, h1out, W1hi, W1lo, bih1, bhh1);
        fc_proj<<<128, 256>>>(h1out, bfc, bpj, xf, y, t);
    }
}

// round 11
// speedup vs baseline: 1.8933x; 1.2315x over previous
#include <cuda_runtime.h>
#include <cuda_bf16.h>
#include <math.h>

// Problem constants
#define Bsz   2048
#define Hh    512
#define DIN   128
#define TT    96
#define DOUT  64

typedef unsigned long long u64;
typedef unsigned int u32;

// ---------------------------------------------------------------------------
// Device-global state & weight scratch
// ---------------------------------------------------------------------------
__device__ __align__(16) float g_h0a[Bsz * Hh];
__device__ __align__(16) float g_h0b[Bsz * Hh];
__device__ __align__(16) float g_h1a[Bsz * Hh];
__device__ __align__(16) float g_h1b[Bsz * Hh];
__device__ __align__(16) float g_xfc[Bsz * DIN];

__device__ __align__(16) float g_Wfc_t[Hh * DIN];   // [k=512][o=128]
__device__ __align__(16) float g_Wpj_t[DIN * DOUT]; // [d=128][o=64]

// Split bf16 GRU weights, augmented K layout: [gate(3)][n(512)][k(KTOT)]
#define K0TOT 640
#define K1TOT 1024
__device__ __align__(16) __nv_bfloat16 g_W0hi[3 * 512 * K0TOT];
__device__ __align__(16) __nv_bfloat16 g_W0lo[3 * 512 * K0TOT];
__device__ __align__(16) __nv_bfloat16 g_W1hi[3 * 512 * K1TOT];
__device__ __align__(16) __nv_bfloat16 g_W1lo[3 * 512 * K1TOT];

// ---------------------------------------------------------------------------
// Helpers
// ---------------------------------------------------------------------------
union F4 { float4 v; float f[4]; u64 d[2]; };

__device__ __forceinline__ u32 smem_to_u32(const void* p) {
    u32 a;
    asm("{ .reg .u64 t; cvta.to.shared.u64 t, %1; cvt.u32.u64 %0, t; }"
        : "=r"(a) : "l"(p));
    return a;
}
__device__ __forceinline__ void cp16(u32 dst, const float4* src) {
    asm volatile("cp.async.cg.shared.global [%0], [%1], 16;"
                 :: "r"(dst), "l"(src));
}
#define CP_COMMIT() asm volatile("cp.async.commit_group;" ::: "memory")
#define CP_WAIT0()  asm volatile("cp.async.wait_group 0;" ::: "memory")

__device__ __forceinline__ void ffma2(u64& acc, u64 a, u64 b) {
    asm("fma.rn.f32x2 %0, %1, %2, %0;" : "+l"(acc) : "l"(a), "l"(b));
}
__device__ __forceinline__ u64 pack2(float x) {
    u64 r; asm("mov.b64 %0, {%1, %1};" : "=l"(r) : "f"(x)); return r;
}
__device__ __forceinline__ float2 unpack2(u64 p) {
    float lo, hi; asm("mov.b64 {%0, %1}, %2;" : "=f"(lo), "=f"(hi) : "l"(p));
    return make_float2(lo, hi);
}
__device__ __forceinline__ float sigf(float x) {
    return __fdividef(1.0f, 1.0f + __expf(-x));
}
__device__ __forceinline__ float tanh_f(float x) {
    return __fdividef(2.0f, 1.0f + __expf(-2.0f * x)) - 1.0f;
}
__device__ __forceinline__ u32 bfpack(float a, float b) {
    __nv_bfloat162 t = __floats2bfloat162_rn(a, b);
    return *(u32*)&t;
}

// m16n8k16 row.col bf16 MMA, fp32 accumulate (sm_80+ baseline ISA)
__device__ __forceinline__ void mma_bf16(float* d, const u32* a, u32 b0, u32 b1) {
    asm volatile(
        "mma.sync.aligned.m16n8k16.row.col.f32.bf16.bf16.f32 "
        "{%0,%1,%2,%3}, {%4,%5,%6,%7}, {%8,%9}, {%0,%1,%2,%3};\n"
        : "+f"(d[0]), "+f"(d[1]), "+f"(d[2]), "+f"(d[3])
        : "r"(a[0]), "r"(a[1]), "r"(a[2]), "r"(a[3]), "r"(b0), "r"(b1));
}

// ---------------------------------------------------------------------------
// Reorg 1: split GRU weights into bf16 hi/lo, augmented-K K-major layout.
// ---------------------------------------------------------------------------
__global__ void pack_weights(const float* __restrict__ Wih0,
                             const float* __restrict__ Whh0,
                             const float* __restrict__ Wih1,
                             const float* __restrict__ Whh1)
{
    int idx = blockIdx.x * blockDim.x + threadIdx.x;
    const int n0 = 3 * 512 * K0TOT;
    const int n1 = 3 * 512 * K1TOT;

    const float *Wih, *Whh;
    int KTOT, XK;
    __nv_bfloat16 *dhi, *dlo;
    if (idx < n0) {
        Wih = Wih0; Whh = Whh0; KTOT = K0TOT; XK = DIN;
        dhi = g_W0hi; dlo = g_W0lo;
    } else {
        idx -= n0;
        if (idx >= n1) return;
        Wih = Wih1; Whh = Whh1; KTOT = K1TOT; XK = 512;
        dhi = g_W1hi; dlo = g_W1lo;
    }

    int k = idx % KTOT;
    int row = idx / KTOT;
    float v = (k < XK) ? Wih[row * XK + k] : Whh[row * 512 + (k - XK)];
    __nv_bfloat16 hi = __float2bfloat16_rn(v);
    dhi[idx] = hi;
    dlo[idx] = __float2bfloat16_rn(v - __bfloat162float(hi));
}

// ---------------------------------------------------------------------------
// Reorg 2: fc/proj transposes + state init
// ---------------------------------------------------------------------------
__global__ void reorg_fc_init(const float* __restrict__ Wfc,
                              const float* __restrict__ Wpj,
                              const float* __restrict__ x)
{
    int idx = blockIdx.x * blockDim.x + threadIdx.x;
    if (idx < Hh * DIN) {
        int k = idx / DIN, n = idx - k * DIN;
        g_Wfc_t[idx] = Wfc[n * Hh + k];
        return;
    }
    idx -= Hh * DIN;
    if (idx < DIN * DOUT) {
        int k = idx / DOUT, n = idx - k * DOUT;
        g_Wpj_t[idx] = Wpj[n * DIN + k];
        return;
    }
    idx -= DIN * DOUT;
    if (idx < Bsz * Hh) {
        g_h0a[idx] = 0.f; g_h1a[idx] = 0.f;
        return;
    }
    idx -= Bsz * Hh;
    if (idx < Bsz * DIN) {
        g_xfc[idx] = x[idx];
    }
}

// ---------------------------------------------------------------------------
// Warp-MMA GRU layer step with double-buffered chunk pipeline.
// Grid 256: mt = bx>>4 (128-batch tile), hc = bx&15 (32 h-cols).
// CTA 256 thr = 8 warps (4 M x 2 HC), warp tile 32x16.
// Planes: 0=r, 1=z, 2=n_ih (x-chunks), 3=n_hh (h-chunks).
// 3-term bf16 split: AhiBhi + AhiBlo + AloBhi.
// Per buffer: A hi/lo [128][72]bf16, B hi/lo [96][72]bf16 = 64512 B.
// Two buffers: B via cp.async into next, A via register-prefetch + convert.
// ---------------------------------------------------------------------------
#define A_HI 0
#define A_LO 18432
#define B_HI 36864
#define B_LO 50688
#define SM_BUF 64512
#define SM_TOTAL 129024

template <int KTOT, int XK, int XSTR>
__global__ void __launch_bounds__(256, 1)
gru_layer_mma(const float* __restrict__ xsrc,
              const float* __restrict__ hin,
              float* __restrict__ hout,
              const __nv_bfloat16* __restrict__ Whi,
              const __nv_bfloat16* __restrict__ Wlo,
              const float* __restrict__ b_ih,
              const float* __restrict__ b_hh)
{
    extern __shared__ char smem[];
    const u32 sb = smem_to_u32(smem);

    const int tid = threadIdx.x;
    const int wid = tid >> 5;
    const int lane = tid & 31;
    const int g_ = lane >> 2;
    const int q_ = lane & 3;
    const int wm = wid & 3;
    const int wn = wid >> 2;
    const int mt = blockIdx.x >> 4;
    const int hc = blockIdx.x & 15;
    const int m0 = mt * 128;
    const int hc0 = hc * 32;

    const int CH = KTOT / 64;
    const int XCH = XK / 64;

    float acc[4][2][2][4];
#pragma unroll
    for (int p = 0; p < 4; ++p)
#pragma unroll
        for (int a = 0; a < 2; ++a)
#pragma unroll
            for (int b = 0; b < 2; ++b)
#pragma unroll
                for (int cc = 0; cc < 4; ++cc) acc[p][a][b][cc] = 0.f;

    F4 pf[8];

    // ---- pipeline helpers (inlined via lambdas) --------------------------
    auto load_A = [&](int c, F4* r) {
        const bool is_x = (c < XCH);
        const float* asrc = is_x ? xsrc : hin;
        const int stride = is_x ? XSTR : 512;
        const int col0 = is_x ? c * 64 : (c - XCH) * 64;
#pragma unroll
        for (int i = 0; i < 8; ++i) {
            const int e = tid + 256 * i;
            const int m = e >> 4, qq = e & 15;
            r[i].v = *(const float4*)&asrc[(m0 + m) * stride + col0 + 4 * qq];
        }
    };
    auto store_A = [&](const F4* r, int buf) {
        u32* AHIp = (u32*)(smem + buf * SM_BUF + A_HI);
        u32* ALOp = (u32*)(smem + buf * SM_BUF + A_LO);
#pragma unroll
        for (int i = 0; i < 8; ++i) {
            const int e = tid + 256 * i;
            const int m = e >> 4, qq = e & 15;
            const F4 v = r[i];
            __nv_bfloat16 h0 = __float2bfloat16_rn(v.f[0]);
            __nv_bfloat16 h1 = __float2bfloat16_rn(v.f[1]);
            __nv_bfloat16 h2 = __float2bfloat16_rn(v.f[2]);
            __nv_bfloat16 h3 = __float2bfloat16_rn(v.f[3]);
            const int o = m * 36 + 2 * qq;
            AHIp[o]     = bfpack(v.f[0], v.f[1]);
            AHIp[o + 1] = bfpack(v.f[2], v.f[3]);
            ALOp[o]     = bfpack(v.f[0] - __bfloat162float(h0),
                                 v.f[1] - __bfloat162float(h1));
            ALOp[o + 1] = bfpack(v.f[2] - __bfloat162float(h2),
                                 v.f[3] - __bfloat162float(h3));
        }
    };
    auto issue_B = [&](int c, int buf) {
        const u32 base = sb + buf * SM_BUF;
#pragma unroll
        for (int i = 0; i < 3; ++i) {
            const int e = tid + 256 * i;
            const int brow = e >> 3, q = e & 7;
            const int gate = brow >> 5, n = brow & 31;
            const long sf4 = ((long)(gate * 512 + hc0 + n) * KTOT + c * 64) / 8 + q;
            cp16(base + B_HI + brow * 144 + q * 16, (const float4*)Whi + sf4);
            cp16(base + B_LO + brow * 144 + q * 16, (const float4*)Wlo + sf4);
        }
    };

    // ---- prologue: fill buffer 0 -----------------------------------------
    load_A(0, pf);
    issue_B(0, 0);
    CP_COMMIT();
    store_A(pf, 0);
    CP_WAIT0();
    __syncthreads();

    // ---- main pipelined chunk loop ---------------------------------------
#pragma unroll 1
    for (int c = 0; c < CH; ++c) {
        const int cur = c & 1;
        const int nxt = cur ^ 1;
        const bool more = (c + 1 < CH);

        if (more) {
            issue_B(c + 1, nxt);
            CP_COMMIT();
            load_A(c + 1, pf);
        }

        // ---- MMA burst on current buffer ---------------------------------
        {
            const u32* AHIp = (const u32*)(smem + cur * SM_BUF + A_HI);
            const u32* ALOp = (const u32*)(smem + cur * SM_BUF + A_LO);
            const u32* BHIp = (const u32*)(smem + cur * SM_BUF + B_HI);
            const u32* BLOp = (const u32*)(smem + cur * SM_BUF + B_LO);
            const bool is_x = (c < XCH);
            const int nplane = is_x ? 2 : 3;
#pragma unroll
            for (int ks = 0; ks < 4; ++ks) {
                const int k0 = ks * 8 + q_;
                u32 a_hi[2][4], a_lo[2][4];
#pragma unroll
                for (int mtl = 0; mtl < 2; ++mtl) {
                    const int r0 = wm * 32 + mtl * 16 + g_;
                    a_hi[mtl][0] = AHIp[r0 * 36 + k0];
                    a_hi[mtl][1] = AHIp[(r0 + 8) * 36 + k0];
                    a_hi[mtl][2] = AHIp[r0 * 36 + k0 + 4];
                    a_hi[mtl][3] = AHIp[(r0 + 8) * 36 + k0 + 4];
                    a_lo[mtl][0] = ALOp[r0 * 36 + k0];
                    a_lo[mtl][1] = ALOp[(r0 + 8) * 36 + k0];
                    a_lo[mtl][2] = ALOp[r0 * 36 + k0 + 4];
                    a_lo[mtl][3] = ALOp[(r0 + 8) * 36 + k0 + 4];
                }
#pragma unroll
                for (int pl = 0; pl < 3; ++pl) {
                    const int gate = (pl == 2) ? 2 : pl;
                    const int ai = (pl == 2) ? nplane : pl;
#pragma unroll
                    for (int nt = 0; nt < 2; ++nt) {
                        const int br = gate * 32 + wn * 16 + nt * 8 + g_;
                        const u32 bh0 = BHIp[br * 36 + k0];
                        const u32 bh1 = BHIp[br * 36 + k0 + 4];
                        const u32 bl0 = BLOp[br * 36 + k0];
                        const u32 bl1 = BLOp[br * 36 + k0 + 4];
#pragma unroll
                        for (int mtl = 0; mtl < 2; ++mtl) {
                            mma_bf16(acc[ai][mtl][nt], a_hi[mtl], bh0, bh1);
                            mma_bf16(acc[ai][mtl][nt], a_hi[mtl], bl0, bl1);
                            mma_bf16(acc[ai][mtl][nt], a_lo[mtl], bh0, bh1);
                        }
                    }
                }
            }
        }

        if (more) {
            store_A(pf, nxt);
            CP_WAIT0();
        }
        __syncthreads();
    }

    // ---- epilogue: gate math + h write ----------------------------------
#pragma unroll
    for (int nt = 0; nt < 2; ++nt) {
        const int j = hc0 + wn * 16 + nt * 8 + 2 * q_;
        const float2 bir = *(const float2*)&b_ih[j];
        const float2 bhr = *(const float2*)&b_hh[j];
        const float2 biz = *(const float2*)&b_ih[512 + j];
        const float2 bhz = *(const float2*)&b_hh[512 + j];
        const float2 bin = *(const float2*)&b_ih[1024 + j];
        const float2 bhn = *(const float2*)&b_hh[1024 + j];
        const float brx = bir.x + bhr.x, bry = bir.y + bhr.y;
        const float bzx = biz.x + bhz.x, bzy = biz.y + bhz.y;
#pragma unroll
        for (int mtl = 0; mtl < 2; ++mtl) {
            const int ra = m0 + wm * 32 + mtl * 16 + g_;
#pragma unroll
            for (int rr = 0; rr < 2; ++rr) {
                const int row = ra + rr * 8;
                const float2 hold = *(const float2*)&hin[row * 512 + j];
                const float r0 = sigf(acc[0][mtl][nt][2 * rr] + brx);
                const float r1 = sigf(acc[0][mtl][nt][2 * rr + 1] + bry);
                const float z0 = sigf(acc[1][mtl][nt][2 * rr] + bzx);
                const float z1 = sigf(acc[1][mtl][nt][2 * rr + 1] + bzy);
                const float n0 = tanh_f(acc[2][mtl][nt][2 * rr] + bin.x
                                        + r0 * (acc[3][mtl][nt][2 * rr] + bhn.x));
                const float n1 = tanh_f(acc[2][mtl][nt][2 * rr + 1] + bin.y
                                        + r1 * (acc[3][mtl][nt][2 * rr + 1] + bhn.y));
                float2 o;
                o.x = n0 + z0 * (hold.x - n0);
                o.y = n1 + z1 * (hold.y - n1);
                *(float2*)&hout[row * 512 + j] = o;
            }
        }
    }
}

// ---------------------------------------------------------------------------
// fc + projection (fp32 / FFMA2), one launch per step. grid 128 x 16 batches.
// ---------------------------------------------------------------------------
__global__ void __launch_bounds__(256, 1)
fc_proj(const float* __restrict__ h1,
        const float* __restrict__ b_fc, const float* __restrict__ b_pj,
        float* __restrict__ xfc, float* __restrict__ y, int t)
{
    __shared__ float sh1[16 * 512];
    __shared__ float sx[16 * 128];
    const int tid = threadIdx.x;
    const int gb0 = blockIdx.x * 16;

    for (int i = tid; i < 8192; i += 256) sh1[i] = h1[gb0 * 512 + i];
    __syncthreads();

    {
        const int ox = tid & 31;
        const int bb = 2 * (tid >> 5);
        u64 acc[2][2] = {{0ull, 0ull}, {0ull, 0ull}};
        const float4* __restrict__ W4 = (const float4*)g_Wfc_t; // [512][32]
#pragma unroll 2
        for (int k = 0; k < Hh; k += 4) {
            F4 hv0, hv1;
            hv0.v = *(const float4*)&sh1[bb * Hh + k];
            hv1.v = *(const float4*)&sh1[(bb + 1) * Hh + k];
#pragma unroll
            for (int kk = 0; kk < 4; ++kk) {
                F4 w; w.v = __ldg(&W4[(k + kk) * 32 + ox]);
                const u64 h0p = pack2(hv0.f[kk]);
                const u64 h1p = pack2(hv1.f[kk]);
                ffma2(acc[0][0], h0p, w.d[0]);
                ffma2(acc[0][1], h0p, w.d[1]);
                ffma2(acc[1][0], h1p, w.d[0]);
                ffma2(acc[1][1], h1p, w.d[1]);
            }
        }
        F4 bf; bf.v = __ldg(((const float4*)b_fc) + ox);
        F4 o0, o1;
#pragma unroll
        for (int p = 0; p < 2; ++p) {
            const float2 a0 = unpack2(acc[0][p]);
            const float2 a1 = unpack2(acc[1][p]);
            o0.f[2 * p] = a0.x + bf.f[2 * p];
            o0.f[2 * p + 1] = a0.y + bf.f[2 * p + 1];
            o1.f[2 * p] = a1.x + bf.f[2 * p];
            o1.f[2 * p + 1] = a1.y + bf.f[2 * p + 1];
        }
        *(float4*)&sx[bb * DIN + 4 * ox]       = o0.v;
        *(float4*)&sx[(bb + 1) * DIN + 4 * ox] = o1.v;
    }
    __syncthreads();

    {
        const int bb = tid >> 4;
        const int ox = tid & 15;
        F4 acc; acc.v = __ldg(((const float4*)b_pj) + ox);
        const float4* __restrict__ W4 = (const float4*)g_Wpj_t; // [128][16]
#pragma unroll 2
        for (int d = 0; d < DIN; d += 4) {
            F4 xv; xv.v = *(const float4*)&sx[bb * DIN + d];
#pragma unroll
            for (int kk = 0; kk < 4; ++kk) {
                F4 w; w.v = __ldg(&W4[(d + kk) * 16 + ox]);
#pragma unroll
                for (int l = 0; l < 4; ++l)
                    acc.f[l] = fmaf(xv.f[kk], w.f[l], acc.f[l]);
            }
        }
        const size_t base = ((size_t)(gb0 + bb) * DOUT + 4 * ox) * TT + t;
        y[base]          = acc.f[0];
        y[base + TT]     = acc.f[1];
        y[base + 2 * TT] = acc.f[2];
        y[base + 3 * TT] = acc.f[3];
    }
    for (int i = tid; i < 2048; i += 256) xfc[gb0 * DIN + i] = sx[i];
}

// ---------------------------------------------------------------------------
// Entry point: 2 reorg + 96 x (layer0, layer1, fc_proj)
// ---------------------------------------------------------------------------
extern "C" void kernel_launch(void* const* d_in, const int* in_sizes, int n_in,
                              void* d_out, int out_size)
{
    (void)in_sizes; (void)n_in; (void)out_size;

    const float* x    = (const float*)d_in[0];
    const float* Wih0 = (const float*)d_in[1];
    const float* Whh0 = (const float*)d_in[2];
    const float* bih0 = (const float*)d_in[3];
    const float* bhh0 = (const float*)d_in[4];
    const float* Wih1 = (const float*)d_in[5];
    const float* Whh1 = (const float*)d_in[6];
    const float* bih1 = (const float*)d_in[7];
    const float* bhh1 = (const float*)d_in[8];
    const float* Wfc  = (const float*)d_in[9];
    const float* bfc  = (const float*)d_in[10];
    const float* Wpj  = (const float*)d_in[11];
    const float* bpj  = (const float*)d_in[12];
    float* y = (float*)d_out;

    float *h0a, *h0b, *h1a, *h1b, *xf;
    __nv_bfloat16 *W0hi, *W0lo, *W1hi, *W1lo;
    cudaGetSymbolAddress((void**)&h0a, g_h0a);
    cudaGetSymbolAddress((void**)&h0b, g_h0b);
    cudaGetSymbolAddress((void**)&h1a, g_h1a);
    cudaGetSymbolAddress((void**)&h1b, g_h1b);
    cudaGetSymbolAddress((void**)&xf,  g_xfc);
    cudaGetSymbolAddress((void**)&W0hi, g_W0hi);
    cudaGetSymbolAddress((void**)&W0lo, g_W0lo);
    cudaGetSymbolAddress((void**)&W1hi, g_W1hi);
    cudaGetSymbolAddress((void**)&W1lo, g_W1lo);

    cudaFuncSetAttribute(gru_layer_mma<K0TOT, DIN, DIN>,
                         cudaFuncAttributeMaxDynamicSharedMemorySize, SM_TOTAL);
    cudaFuncSetAttribute(gru_layer_mma<K1TOT, 512, 512>,
                         cudaFuncAttributeMaxDynamicSharedMemorySize, SM_TOTAL);

    {
        const int total = 3 * 512 * K0TOT + 3 * 512 * K1TOT;
        pack_weights<<<(total + 255) / 256, 256>>>(Wih0, Whh0, Wih1, Whh1);
    }
    {
        const int total = Hh * DIN + DIN * DOUT + Bsz * Hh + Bsz * DIN;
        reorg_fc_init<<<(total + 255) / 256, 256>>>(Wfc, Wpj, x);
    }

    for (int t = 0; t < TT; ++t) {
        const int ping = t & 1;
        const float* h0in = ping ? h0b : h0a;
        float*       h0out = ping ? h0a : h0b;
        const float* h1in = ping ? h1b : h1a;
        float*       h1out = ping ? h1a : h1b;

        gru_layer_mma<K0TOT, DIN, DIN><<<256, 256, SM_TOTAL>>>(
            xf, h0in, h0out, W0hi, W0lo, bih0, bhh0);
        gru_layer_mma<K1TOT, 512, 512><<<256, 256, SM_TOTAL>>>(
            h0out, h1in, h1out, W1hi, W1lo, bih1, bhh1);
        fc_proj<<<128, 256>>>(h1out, bfc, bpj, xf, y, t);
    }
}

// round 12
// speedup vs baseline: 1.9724x; 1.0418x over previous
#include <cuda_runtime.h>
#include <cuda_bf16.h>
#include <math.h>

// Problem constants
#define Bsz   2048
#define Hh    512
#define DIN   128
#define TT    96
#define DOUT  64

typedef unsigned long long u64;
typedef unsigned int u32;

// ---------------------------------------------------------------------------
// Device-global state & weight scratch
// ---------------------------------------------------------------------------
__device__ __align__(16) float g_h0a[Bsz * Hh];
__device__ __align__(16) float g_h0b[Bsz * Hh];
__device__ __align__(16) float g_h1a[Bsz * Hh];
__device__ __align__(16) float g_h1b[Bsz * Hh];
__device__ __align__(16) float g_xfc[Bsz * DIN];

// Pre-split bf16 images of the activations (written by producers)
__device__ __align__(16) __nv_bfloat16 g_h0hi_a[Bsz * Hh];
__device__ __align__(16) __nv_bfloat16 g_h0lo_a[Bsz * Hh];
__device__ __align__(16) __nv_bfloat16 g_h0hi_b[Bsz * Hh];
__device__ __align__(16) __nv_bfloat16 g_h0lo_b[Bsz * Hh];
__device__ __align__(16) __nv_bfloat16 g_h1hi_a[Bsz * Hh];
__device__ __align__(16) __nv_bfloat16 g_h1lo_a[Bsz * Hh];
__device__ __align__(16) __nv_bfloat16 g_h1hi_b[Bsz * Hh];
__device__ __align__(16) __nv_bfloat16 g_h1lo_b[Bsz * Hh];
__device__ __align__(16) __nv_bfloat16 g_xfchi[Bsz * DIN];
__device__ __align__(16) __nv_bfloat16 g_xfclo[Bsz * DIN];

__device__ __align__(16) float g_Wfc_t[Hh * DIN];   // [k=512][o=128]
__device__ __align__(16) float g_Wpj_t[DIN * DOUT]; // [d=128][o=64]

// Split bf16 GRU weights, augmented K layout: [gate(3)][n(512)][k(KTOT)]
#define K0TOT 640
#define K1TOT 1024
__device__ __align__(16) __nv_bfloat16 g_W0hi[3 * 512 * K0TOT];
__device__ __align__(16) __nv_bfloat16 g_W0lo[3 * 512 * K0TOT];
__device__ __align__(16) __nv_bfloat16 g_W1hi[3 * 512 * K1TOT];
__device__ __align__(16) __nv_bfloat16 g_W1lo[3 * 512 * K1TOT];

// ---------------------------------------------------------------------------
// Helpers
// ---------------------------------------------------------------------------
union F4 { float4 v; float f[4]; u64 d[2]; };

__device__ __forceinline__ u32 smem_to_u32(const void* p) {
    u32 a;
    asm("{ .reg .u64 t; cvta.to.shared.u64 t, %1; cvt.u32.u64 %0, t; }"
        : "=r"(a) : "l"(p));
    return a;
}
__device__ __forceinline__ void cp16(u32 dst, const void* src) {
    asm volatile("cp.async.cg.shared.global [%0], [%1], 16;"
                 :: "r"(dst), "l"(src));
}
#define CP_COMMIT() asm volatile("cp.async.commit_group;" ::: "memory")
#define CP_WAIT0()  asm volatile("cp.async.wait_group 0;" ::: "memory")

__device__ __forceinline__ void ffma2(u64& acc, u64 a, u64 b) {
    asm("fma.rn.f32x2 %0, %1, %2, %0;" : "+l"(acc) : "l"(a), "l"(b));
}
__device__ __forceinline__ u64 pack2(float x) {
    u64 r; asm("mov.b64 %0, {%1, %1};" : "=l"(r) : "f"(x)); return r;
}
__device__ __forceinline__ float2 unpack2(u64 p) {
    float lo, hi; asm("mov.b64 {%0, %1}, %2;" : "=f"(lo), "=f"(hi) : "l"(p));
    return make_float2(lo, hi);
}
__device__ __forceinline__ float sigf(float x) {
    return __fdividef(1.0f, 1.0f + __expf(-x));
}
__device__ __forceinline__ float tanh_f(float x) {
    return __fdividef(2.0f, 1.0f + __expf(-2.0f * x)) - 1.0f;
}
__device__ __forceinline__ u32 bfpack(float a, float b) {
    __nv_bfloat162 t = __floats2bfloat162_rn(a, b);
    return *(u32*)&t;
}

// m16n8k16 row.col bf16 MMA, fp32 accumulate (sm_80+ baseline ISA)
__device__ __forceinline__ void mma_bf16(float* d, const u32* a, u32 b0, u32 b1) {
    asm volatile(
        "mma.sync.aligned.m16n8k16.row.col.f32.bf16.bf16.f32 "
        "{%0,%1,%2,%3}, {%4,%5,%6,%7}, {%8,%9}, {%0,%1,%2,%3};\n"
        : "+f"(d[0]), "+f"(d[1]), "+f"(d[2]), "+f"(d[3])
        : "r"(a[0]), "r"(a[1]), "r"(a[2]), "r"(a[3]), "r"(b0), "r"(b1));
}

// ---------------------------------------------------------------------------
// Reorg 1: split GRU weights into bf16 hi/lo, augmented-K K-major layout.
// ---------------------------------------------------------------------------
__global__ void pack_weights(const float* __restrict__ Wih0,
                             const float* __restrict__ Whh0,
                             const float* __restrict__ Wih1,
                             const float* __restrict__ Whh1)
{
    int idx = blockIdx.x * blockDim.x + threadIdx.x;
    const int n0 = 3 * 512 * K0TOT;
    const int n1 = 3 * 512 * K1TOT;

    const float *Wih, *Whh;
    int KTOT, XK;
    __nv_bfloat16 *dhi, *dlo;
    if (idx < n0) {
        Wih = Wih0; Whh = Whh0; KTOT = K0TOT; XK = DIN;
        dhi = g_W0hi; dlo = g_W0lo;
    } else {
        idx -= n0;
        if (idx >= n1) return;
        Wih = Wih1; Whh = Whh1; KTOT = K1TOT; XK = 512;
        dhi = g_W1hi; dlo = g_W1lo;
    }

    int k = idx % KTOT;
    int row = idx / KTOT;
    float v = (k < XK) ? Wih[row * XK + k] : Whh[row * 512 + (k - XK)];
    __nv_bfloat16 hi = __float2bfloat16_rn(v);
    dhi[idx] = hi;
    dlo[idx] = __float2bfloat16_rn(v - __bfloat162float(hi));
}

// ---------------------------------------------------------------------------
// Reorg 2: fc/proj transposes + state init (f32 + split images)
// ---------------------------------------------------------------------------
__global__ void reorg_fc_init(const float* __restrict__ Wfc,
                              const float* __restrict__ Wpj,
                              const float* __restrict__ x)
{
    int idx = blockIdx.x * blockDim.x + threadIdx.x;
    if (idx < Hh * DIN) {
        int k = idx / DIN, n = idx - k * DIN;
        g_Wfc_t[idx] = Wfc[n * Hh + k];
        return;
    }
    idx -= Hh * DIN;
    if (idx < DIN * DOUT) {
        int k = idx / DOUT, n = idx - k * DOUT;
        g_Wpj_t[idx] = Wpj[n * DIN + k];
        return;
    }
    idx -= DIN * DOUT;
    if (idx < Bsz * Hh) {
        g_h0a[idx] = 0.f; g_h1a[idx] = 0.f;
        __nv_bfloat16 z = __float2bfloat16_rn(0.f);
        g_h0hi_a[idx] = z; g_h0lo_a[idx] = z;
        g_h1hi_a[idx] = z; g_h1lo_a[idx] = z;
        return;
    }
    idx -= Bsz * Hh;
    if (idx < Bsz * DIN) {
        float v = x[idx];
        g_xfc[idx] = v;
        __nv_bfloat16 hi = __float2bfloat16_rn(v);
        g_xfchi[idx] = hi;
        g_xfclo[idx] = __float2bfloat16_rn(v - __bfloat162float(hi));
    }
}

// ---------------------------------------------------------------------------
// Warp-MMA GRU layer step, pre-split A, single 64.5KB buffer, 2 CTAs/SM.
// Grid 256: mt = bx>>4 (128-batch tile), hc = bx&15 (32 h-cols).
// CTA 256 thr = 8 warps (4 M x 2 HC), warp tile 32x16.
// Planes: 0=r, 1=z, 2=n_ih (x-chunks), 3=n_hh (h-chunks).
// 3-term bf16 split: AhiBhi + AhiBlo + AloBhi.
// smem: A hi/lo [128][72]bf16, B hi/lo [96][72]bf16 = 64512 B (rows 144B=36u32)
// ---------------------------------------------------------------------------
#define A_HI 0
#define A_LO 18432
#define B_HI 36864
#define B_LO 50688
#define SM_TOTAL 64512

template <int KTOT, int XK>
__global__ void __launch_bounds__(256, 2)
gru_layer_mma(const __nv_bfloat16* __restrict__ xhi,
              const __nv_bfloat16* __restrict__ xlo,
              const __nv_bfloat16* __restrict__ hhi,
              const __nv_bfloat16* __restrict__ hlo,
              const float* __restrict__ hin,
              float* __restrict__ hout,
              u32* __restrict__ houthi,    // bf16x2 image of hout
              u32* __restrict__ houtlo,
              const __nv_bfloat16* __restrict__ Whi,
              const __nv_bfloat16* __restrict__ Wlo,
              const float* __restrict__ b_ih,
              const float* __restrict__ b_hh)
{
    extern __shared__ char smem[];
    const u32 sb = smem_to_u32(smem);
    const u32* AHIp = (const u32*)(smem + A_HI);
    const u32* ALOp = (const u32*)(smem + A_LO);
    const u32* BHIp = (const u32*)(smem + B_HI);
    const u32* BLOp = (const u32*)(smem + B_LO);

    const int tid = threadIdx.x;
    const int wid = tid >> 5;
    const int lane = tid & 31;
    const int g_ = lane >> 2;
    const int q_ = lane & 3;
    const int wm = wid & 3;
    const int wn = wid >> 2;
    const int mt = blockIdx.x >> 4;
    const int hc = blockIdx.x & 15;
    const int m0 = mt * 128;
    const int hc0 = hc * 32;

    const int CH = KTOT / 64;
    const int XCH = XK / 64;

    float acc[4][2][2][4];
#pragma unroll
    for (int p = 0; p < 4; ++p)
#pragma unroll
        for (int a = 0; a < 2; ++a)
#pragma unroll
            for (int b = 0; b < 2; ++b)
#pragma unroll
                for (int cc = 0; cc < 4; ++cc) acc[p][a][b][cc] = 0.f;

#pragma unroll 1
    for (int c = 0; c < CH; ++c) {
        const bool is_x = (c < XCH);
        // ---- fill: A + B via cp.async (no conversion — pre-split) --------
        {
            const __nv_bfloat16* ahi = is_x ? xhi : hhi;
            const __nv_bfloat16* alo = is_x ? xlo : hlo;
            const int stride = is_x ? XK : 512;
            const int col0 = is_x ? c * 64 : (c - XCH) * 64;
#pragma unroll
            for (int i = 0; i < 4; ++i) {
                const int e = tid + 256 * i;
                const int m = e >> 3, q = e & 7;
                const long so = (long)(m0 + m) * stride + col0 + q * 8;
                const u32 doff = m * 144 + q * 16;
                cp16(sb + A_HI + doff, ahi + so);
                cp16(sb + A_LO + doff, alo + so);
            }
#pragma unroll
            for (int i = 0; i < 3; ++i) {
                const int e = tid + 256 * i;
                const int brow = e >> 3, q = e & 7;
                const int gate = brow >> 5, n = brow & 31;
                const long so = (long)(gate * 512 + hc0 + n) * KTOT + c * 64 + q * 8;
                const u32 doff = brow * 144 + q * 16;
                cp16(sb + B_HI + doff, Whi + so);
                cp16(sb + B_LO + doff, Wlo + so);
            }
            CP_COMMIT();
            CP_WAIT0();
            __syncthreads();
        }

        // ---- MMA burst ----------------------------------------------------
        {
            const int nplane = is_x ? 2 : 3;
#pragma unroll
            for (int ks = 0; ks < 4; ++ks) {
                const int k0 = ks * 8 + q_;
#pragma unroll
                for (int mtl = 0; mtl < 2; ++mtl) {
                    const int r0 = wm * 32 + mtl * 16 + g_;
                    u32 a_hi[4], a_lo[4];
                    a_hi[0] = AHIp[r0 * 36 + k0];
                    a_hi[1] = AHIp[(r0 + 8) * 36 + k0];
                    a_hi[2] = AHIp[r0 * 36 + k0 + 4];
                    a_hi[3] = AHIp[(r0 + 8) * 36 + k0 + 4];
                    a_lo[0] = ALOp[r0 * 36 + k0];
                    a_lo[1] = ALOp[(r0 + 8) * 36 + k0];
                    a_lo[2] = ALOp[r0 * 36 + k0 + 4];
                    a_lo[3] = ALOp[(r0 + 8) * 36 + k0 + 4];
#pragma unroll
                    for (int pl = 0; pl < 3; ++pl) {
                        const int gate = (pl == 2) ? 2 : pl;
                        const int ai = (pl == 2) ? nplane : pl;
#pragma unroll
                        for (int nt = 0; nt < 2; ++nt) {
                            const int br = gate * 32 + wn * 16 + nt * 8 + g_;
                            const u32 bh0 = BHIp[br * 36 + k0];
                            const u32 bh1 = BHIp[br * 36 + k0 + 4];
                            const u32 bl0 = BLOp[br * 36 + k0];
                            const u32 bl1 = BLOp[br * 36 + k0 + 4];
                            mma_bf16(acc[ai][mtl][nt], a_hi, bh0, bh1);
                            mma_bf16(acc[ai][mtl][nt], a_hi, bl0, bl1);
                            mma_bf16(acc[ai][mtl][nt], a_lo, bh0, bh1);
                        }
                    }
                }
            }
        }
        __syncthreads();
    }

    // ---- epilogue: gate math + h write (f32 + split images) --------------
#pragma unroll
    for (int nt = 0; nt < 2; ++nt) {
        const int j = hc0 + wn * 16 + nt * 8 + 2 * q_;
        const float2 bir = *(const float2*)&b_ih[j];
        const float2 bhr = *(const float2*)&b_hh[j];
        const float2 biz = *(const float2*)&b_ih[512 + j];
        const float2 bhz = *(const float2*)&b_hh[512 + j];
        const float2 bin = *(const float2*)&b_ih[1024 + j];
        const float2 bhn = *(const float2*)&b_hh[1024 + j];
        const float brx = bir.x + bhr.x, bry = bir.y + bhr.y;
        const float bzx = biz.x + bhz.x, bzy = biz.y + bhz.y;
#pragma unroll
        for (int mtl = 0; mtl < 2; ++mtl) {
            const int ra = m0 + wm * 32 + mtl * 16 + g_;
#pragma unroll
            for (int rr = 0; rr < 2; ++rr) {
                const int row = ra + rr * 8;
                const float2 hold = *(const float2*)&hin[row * 512 + j];
                const float r0 = sigf(acc[0][mtl][nt][2 * rr] + brx);
                const float r1 = sigf(acc[0][mtl][nt][2 * rr + 1] + bry);
                const float z0 = sigf(acc[1][mtl][nt][2 * rr] + bzx);
                const float z1 = sigf(acc[1][mtl][nt][2 * rr + 1] + bzy);
                const float n0 = tanh_f(acc[2][mtl][nt][2 * rr] + bin.x
                                        + r0 * (acc[3][mtl][nt][2 * rr] + bhn.x));
                const float n1 = tanh_f(acc[2][mtl][nt][2 * rr + 1] + bin.y
                                        + r1 * (acc[3][mtl][nt][2 * rr + 1] + bhn.y));
                float2 o;
                o.x = n0 + z0 * (hold.x - n0);
                o.y = n1 + z1 * (hold.y - n1);
                *(float2*)&hout[row * 512 + j] = o;
                __nv_bfloat16 hx = __float2bfloat16_rn(o.x);
                __nv_bfloat16 hy = __float2bfloat16_rn(o.y);
                const int pi = (row * 512 + j) >> 1;
                houthi[pi] = bfpack(o.x, o.y);
                houtlo[pi] = bfpack(o.x - __bfloat162float(hx),
                                    o.y - __bfloat162float(hy));
            }
        }
    }
}

// ---------------------------------------------------------------------------
// fc + projection (fp32 / FFMA2), one launch per step. grid 128 x 16 batches.
// Also writes xfc split images for the next step's layer0.
// ---------------------------------------------------------------------------
__global__ void __launch_bounds__(256, 1)
fc_proj(const float* __restrict__ h1,
        const float* __restrict__ b_fc, const float* __restrict__ b_pj,
        float* __restrict__ xfc,
        u32* __restrict__ xfchi, u32* __restrict__ xfclo,
        float* __restrict__ y, int t)
{
    __shared__ float sh1[16 * 512];
    __shared__ float sx[16 * 128];
    const int tid = threadIdx.x;
    const int gb0 = blockIdx.x * 16;

    for (int i = tid; i < 8192; i += 256) sh1[i] = h1[gb0 * 512 + i];
    __syncthreads();

    {
        const int ox = tid & 31;
        const int bb = 2 * (tid >> 5);
        u64 acc[2][2] = {{0ull, 0ull}, {0ull, 0ull}};
        const float4* __restrict__ W4 = (const float4*)g_Wfc_t; // [512][32]
#pragma unroll 2
        for (int k = 0; k < Hh; k += 4) {
            F4 hv0, hv1;
            hv0.v = *(const float4*)&sh1[bb * Hh + k];
            hv1.v = *(const float4*)&sh1[(bb + 1) * Hh + k];
#pragma unroll
            for (int kk = 0; kk < 4; ++kk) {
                F4 w; w.v = __ldg(&W4[(k + kk) * 32 + ox]);
                const u64 h0p = pack2(hv0.f[kk]);
                const u64 h1p = pack2(hv1.f[kk]);
                ffma2(acc[0][0], h0p, w.d[0]);
                ffma2(acc[0][1], h0p, w.d[1]);
                ffma2(acc[1][0], h1p, w.d[0]);
                ffma2(acc[1][1], h1p, w.d[1]);
            }
        }
        F4 bf; bf.v = __ldg(((const float4*)b_fc) + ox);
        F4 o0, o1;
#pragma unroll
        for (int p = 0; p < 2; ++p) {
            const float2 a0 = unpack2(acc[0][p]);
            const float2 a1 = unpack2(acc[1][p]);
            o0.f[2 * p] = a0.x + bf.f[2 * p];
            o0.f[2 * p + 1] = a0.y + bf.f[2 * p + 1];
            o1.f[2 * p] = a1.x + bf.f[2 * p];
            o1.f[2 * p + 1] = a1.y + bf.f[2 * p + 1];
        }
        *(float4*)&sx[bb * DIN + 4 * ox]       = o0.v;
        *(float4*)&sx[(bb + 1) * DIN + 4 * ox] = o1.v;
    }
    __syncthreads();

    {
        const int bb = tid >> 4;
        const int ox = tid & 15;
        F4 acc; acc.v = __ldg(((const float4*)b_pj) + ox);
        const float4* __restrict__ W4 = (const float4*)g_Wpj_t; // [128][16]
#pragma unroll 2
        for (int d = 0; d < DIN; d += 4) {
            F4 xv; xv.v = *(const float4*)&sx[bb * DIN + d];
#pragma unroll
            for (int kk = 0; kk < 4; ++kk) {
                F4 w; w.v = __ldg(&W4[(d + kk) * 16 + ox]);
#pragma unroll
                for (int l = 0; l < 4; ++l)
                    acc.f[l] = fmaf(xv.f[kk], w.f[l], acc.f[l]);
            }
        }
        const size_t base = ((size_t)(gb0 + bb) * DOUT + 4 * ox) * TT + t;
        y[base]          = acc.f[0];
        y[base + TT]     = acc.f[1];
        y[base + 2 * TT] = acc.f[2];
        y[base + 3 * TT] = acc.f[3];
    }
    // xfc writeback: f32 + split bf16 images
    for (int i = tid; i < 1024; i += 256) {
        float2 v = *(float2*)&sx[2 * i];
        *(float2*)&xfc[gb0 * DIN + 2 * i] = v;
        __nv_bfloat16 hx = __float2bfloat16_rn(v.x);
        __nv_bfloat16 hy = __float2bfloat16_rn(v.y);
        xfchi[gb0 * 64 + i] = bfpack(v.x, v.y);
        xfclo[gb0 * 64 + i] = bfpack(v.x - __bfloat162float(hx),
                                     v.y - __bfloat162float(hy));
    }
}

// ---------------------------------------------------------------------------
// Entry point: 2 reorg + 96 x (layer0, layer1, fc_proj)
// ---------------------------------------------------------------------------
extern "C" void kernel_launch(void* const* d_in, const int* in_sizes, int n_in,
                              void* d_out, int out_size)
{
    (void)in_sizes; (void)n_in; (void)out_size;

    const float* x    = (const float*)d_in[0];
    const float* Wih0 = (const float*)d_in[1];
    const float* Whh0 = (const float*)d_in[2];
    const float* bih0 = (const float*)d_in[3];
    const float* bhh0 = (const float*)d_in[4];
    const float* Wih1 = (const float*)d_in[5];
    const float* Whh1 = (const float*)d_in[6];
    const float* bih1 = (const float*)d_in[7];
    const float* bhh1 = (const float*)d_in[8];
    const float* Wfc  = (const float*)d_in[9];
    const float* bfc  = (const float*)d_in[10];
    const float* Wpj  = (const float*)d_in[11];
    const float* bpj  = (const float*)d_in[12];
    float* y = (float*)d_out;

    float *h0a, *h0b, *h1a, *h1b, *xf;
    __nv_bfloat16 *W0hi, *W0lo, *W1hi, *W1lo;
    __nv_bfloat16 *h0hiA, *h0loA, *h0hiB, *h0loB;
    __nv_bfloat16 *h1hiA, *h1loA, *h1hiB, *h1loB;
    __nv_bfloat16 *xfhi, *xflo;
    cudaGetSymbolAddress((void**)&h0a, g_h0a);
    cudaGetSymbolAddress((void**)&h0b, g_h0b);
    cudaGetSymbolAddress((void**)&h1a, g_h1a);
    cudaGetSymbolAddress((void**)&h1b, g_h1b);
    cudaGetSymbolAddress((void**)&xf,  g_xfc);
    cudaGetSymbolAddress((void**)&W0hi, g_W0hi);
    cudaGetSymbolAddress((void**)&W0lo, g_W0lo);
    cudaGetSymbolAddress((void**)&W1hi, g_W1hi);
    cudaGetSymbolAddress((void**)&W1lo, g_W1lo);
    cudaGetSymbolAddress((void**)&h0hiA, g_h0hi_a);
    cudaGetSymbolAddress((void**)&h0loA, g_h0lo_a);
    cudaGetSymbolAddress((void**)&h0hiB, g_h0hi_b);
    cudaGetSymbolAddress((void**)&h0loB, g_h0lo_b);
    cudaGetSymbolAddress((void**)&h1hiA, g_h1hi_a);
    cudaGetSymbolAddress((void**)&h1loA, g_h1lo_a);
    cudaGetSymbolAddress((void**)&h1hiB, g_h1hi_b);
    cudaGetSymbolAddress((void**)&h1loB, g_h1lo_b);
    cudaGetSymbolAddress((void**)&xfhi, g_xfchi);
    cudaGetSymbolAddress((void**)&xflo, g_xfclo);

    cudaFuncSetAttribute(gru_layer_mma<K0TOT, DIN>,
                         cudaFuncAttributeMaxDynamicSharedMemorySize, SM_TOTAL);
    cudaFuncSetAttribute(gru_layer_mma<K1TOT, 512>,
                         cudaFuncAttributeMaxDynamicSharedMemorySize, SM_TOTAL);

    {
        const int total = 3 * 512 * K0TOT + 3 * 512 * K1TOT;
        pack_weights<<<(total + 255) / 256, 256>>>(Wih0, Whh0, Wih1, Whh1);
    }
    {
        const int total = Hh * DIN + DIN * DOUT + Bsz * Hh + Bsz * DIN;
        reorg_fc_init<<<(total + 255) / 256, 256>>>(Wfc, Wpj, x);
    }

    for (int t = 0; t < TT; ++t) {
        const int ping = t & 1;
        const float* h0in = ping ? h0b : h0a;
        float*       h0out = ping ? h0a : h0b;
        const float* h1in = ping ? h1b : h1a;
        float*       h1out = ping ? h1a : h1b;
        const __nv_bfloat16* h0hi_in = ping ? h0hiB : h0hiA;
        const __nv_bfloat16* h0lo_in = ping ? h0loB : h0loA;
        __nv_bfloat16* h0hi_out = ping ? h0hiA : h0hiB;
        __nv_bfloat16* h0lo_out = ping ? h0loA : h0loB;
        const __nv_bfloat16* h1hi_in = ping ? h1hiB : h1hiA;
        const __nv_bfloat16* h1lo_in = ping ? h1loB : h1loA;
        __nv_bfloat16* h1hi_out = ping ? h1hiA : h1hiB;
        __nv_bfloat16* h1lo_out = ping ? h1loA : h1loB;

        gru_layer_mma<K0TOT, DIN><<<256, 256, SM_TOTAL>>>(
            xfhi, xflo, h0hi_in, h0lo_in, h0in,
            h0out, (u32*)h0hi_out, (u32*)h0lo_out,
            W0hi, W0lo, bih0, bhh0);
        gru_layer_mma<K1TOT, 512><<<256, 256, SM_TOTAL>>>(
            h0hi_out, h0lo_out, h1hi_in, h1lo_in, h1in,
            h1out, (u32*)h1hi_out, (u32*)h1lo_out,
            W1hi, W1lo, bih1, bhh1);
        fc_proj<<<128, 256>>>(h1out, bfc, bpj, xf,
                              (u32*)xfhi, (u32*)xflo, y, t);
    }
}

// round 15
// speedup vs baseline: 2.0150x; 1.0216x over previous
#include <cuda_runtime.h>
#include <cuda_bf16.h>
#include <math.h>

// Problem constants
#define Bsz   2048
#define Hh    512
#define DIN   128
#define TT    96
#define DOUT  64

typedef unsigned long long u64;
typedef unsigned int u32;

// ---------------------------------------------------------------------------
// Device-global state & weight scratch
// ---------------------------------------------------------------------------
__device__ __align__(16) float g_h0a[Bsz * Hh];
__device__ __align__(16) float g_h0b[Bsz * Hh];
__device__ __align__(16) float g_h1a[Bsz * Hh];
__device__ __align__(16) float g_h1b[Bsz * Hh];
__device__ __align__(16) float g_xfc[Bsz * DIN];

// Pre-split bf16 images of the activations (written by producers)
__device__ __align__(16) __nv_bfloat16 g_h0hi_a[Bsz * Hh];
__device__ __align__(16) __nv_bfloat16 g_h0lo_a[Bsz * Hh];
__device__ __align__(16) __nv_bfloat16 g_h0hi_b[Bsz * Hh];
__device__ __align__(16) __nv_bfloat16 g_h0lo_b[Bsz * Hh];
__device__ __align__(16) __nv_bfloat16 g_h1hi_a[Bsz * Hh];
__device__ __align__(16) __nv_bfloat16 g_h1lo_a[Bsz * Hh];
__device__ __align__(16) __nv_bfloat16 g_h1hi_b[Bsz * Hh];
__device__ __align__(16) __nv_bfloat16 g_h1lo_b[Bsz * Hh];
__device__ __align__(16) __nv_bfloat16 g_xfchi[Bsz * DIN];
__device__ __align__(16) __nv_bfloat16 g_xfclo[Bsz * DIN];

__device__ __align__(16) float g_Wfc_t[Hh * DIN];   // [k=512][o=128]
__device__ __align__(16) float g_Wpj_t[DIN * DOUT]; // [d=128][o=64]

// Split bf16 GRU weights, augmented K layout: [gate(3)][n(512)][k(KTOT)]
#define K0TOT 640
#define K1TOT 1024
__device__ __align__(16) __nv_bfloat16 g_W0hi[3 * 512 * K0TOT];
__device__ __align__(16) __nv_bfloat16 g_W0lo[3 * 512 * K0TOT];
__device__ __align__(16) __nv_bfloat16 g_W1hi[3 * 512 * K1TOT];
__device__ __align__(16) __nv_bfloat16 g_W1lo[3 * 512 * K1TOT];

// ---------------------------------------------------------------------------
// Helpers
// ---------------------------------------------------------------------------
union F4 { float4 v; float f[4]; u64 d[2]; };

__device__ __forceinline__ u32 smem_to_u32(const void* p) {
    u32 a;
    asm("{ .reg .u64 t; cvta.to.shared.u64 t, %1; cvt.u32.u64 %0, t; }"
        : "=r"(a) : "l"(p));
    return a;
}
__device__ __forceinline__ void cp16(u32 dst, const void* src) {
    asm volatile("cp.async.cg.shared.global [%0], [%1], 16;"
                 :: "r"(dst), "l"(src));
}
#define CP_COMMIT() asm volatile("cp.async.commit_group;" ::: "memory")
#define CP_WAIT0()  asm volatile("cp.async.wait_group 0;" ::: "memory")

__device__ __forceinline__ void ffma2(u64& acc, u64 a, u64 b) {
    asm("fma.rn.f32x2 %0, %1, %2, %0;" : "+l"(acc) : "l"(a), "l"(b));
}
__device__ __forceinline__ u64 pack2(float x) {
    u64 r; asm("mov.b64 %0, {%1, %1};" : "=l"(r) : "f"(x)); return r;
}
__device__ __forceinline__ float2 unpack2(u64 p) {
    float lo, hi; asm("mov.b64 {%0, %1}, %2;" : "=f"(lo), "=f"(hi) : "l"(p));
    return make_float2(lo, hi);
}
__device__ __forceinline__ float sigf(float x) {
    return __fdividef(1.0f, 1.0f + __expf(-x));
}
__device__ __forceinline__ float tanh_f(float x) {
    return __fdividef(2.0f, 1.0f + __expf(-2.0f * x)) - 1.0f;
}
__device__ __forceinline__ u32 bfpack(float a, float b) {
    __nv_bfloat162 t = __floats2bfloat162_rn(a, b);
    return *(u32*)&t;
}

// m16n8k16 row.col bf16 MMA, fp32 accumulate (sm_80+ baseline ISA)
__device__ __forceinline__ void mma_bf16(float* d, const u32* a, u32 b0, u32 b1) {
    asm volatile(
        "mma.sync.aligned.m16n8k16.row.col.f32.bf16.bf16.f32 "
        "{%0,%1,%2,%3}, {%4,%5,%6,%7}, {%8,%9}, {%0,%1,%2,%3};\n"
        : "+f"(d[0]), "+f"(d[1]), "+f"(d[2]), "+f"(d[3])
        : "r"(a[0]), "r"(a[1]), "r"(a[2]), "r"(a[3]), "r"(b0), "r"(b1));
}

// ---------------------------------------------------------------------------
// Reorg 1: split GRU weights into bf16 hi/lo, augmented-K K-major layout.
// ---------------------------------------------------------------------------
__global__ void pack_weights(const float* __restrict__ Wih0,
                             const float* __restrict__ Whh0,
                             const float* __restrict__ Wih1,
                             const float* __restrict__ Whh1)
{
    int idx = blockIdx.x * blockDim.x + threadIdx.x;
    const int n0 = 3 * 512 * K0TOT;
    const int n1 = 3 * 512 * K1TOT;

    const float *Wih, *Whh;
    int KTOT, XK;
    __nv_bfloat16 *dhi, *dlo;
    if (idx < n0) {
        Wih = Wih0; Whh = Whh0; KTOT = K0TOT; XK = DIN;
        dhi = g_W0hi; dlo = g_W0lo;
    } else {
        idx -= n0;
        if (idx >= n1) return;
        Wih = Wih1; Whh = Whh1; KTOT = K1TOT; XK = 512;
        dhi = g_W1hi; dlo = g_W1lo;
    }

    int k = idx % KTOT;
    int row = idx / KTOT;
    float v = (k < XK) ? Wih[row * XK + k] : Whh[row * 512 + (k - XK)];
    __nv_bfloat16 hi = __float2bfloat16_rn(v);
    dhi[idx] = hi;
    dlo[idx] = __float2bfloat16_rn(v - __bfloat162float(hi));
}

// ---------------------------------------------------------------------------
// Reorg 2: fc/proj transposes + state init (f32 + split images)
// ---------------------------------------------------------------------------
__global__ void reorg_fc_init(const float* __restrict__ Wfc,
                              const float* __restrict__ Wpj,
                              const float* __restrict__ x)
{
    int idx = blockIdx.x * blockDim.x + threadIdx.x;
    if (idx < Hh * DIN) {
        int k = idx / DIN, n = idx - k * DIN;
        g_Wfc_t[idx] = Wfc[n * Hh + k];
        return;
    }
    idx -= Hh * DIN;
    if (idx < DIN * DOUT) {
        int k = idx / DOUT, n = idx - k * DOUT;
        g_Wpj_t[idx] = Wpj[n * DIN + k];
        return;
    }
    idx -= DIN * DOUT;
    if (idx < Bsz * Hh) {
        g_h0a[idx] = 0.f; g_h1a[idx] = 0.f;
        __nv_bfloat16 z = __float2bfloat16_rn(0.f);
        g_h0hi_a[idx] = z; g_h0lo_a[idx] = z;
        g_h1hi_a[idx] = z; g_h1lo_a[idx] = z;
        return;
    }
    idx -= Bsz * Hh;
    if (idx < Bsz * DIN) {
        float v = x[idx];
        g_xfc[idx] = v;
        __nv_bfloat16 hi = __float2bfloat16_rn(v);
        g_xfchi[idx] = hi;
        g_xfclo[idx] = __float2bfloat16_rn(v - __bfloat162float(hi));
    }
}

// ---------------------------------------------------------------------------
// Warp-MMA GRU layer step: pre-split A + K=32 double-buffered pipeline,
// 2 CTAs/SM.
// Grid 256: mt = bx>>4 (128-batch tile), hc = bx&15 (32 h-cols).
// CTA 256 thr = 8 warps (4 M x 2 HC), warp tile 32x16.
// Planes: 0=r, 1=z, 2=n_ih (x-chunks), 3=n_hh (h-chunks).
// 3-term bf16 split: AhiBhi + AhiBlo + AloBhi.
// Per buffer (K=32 chunk): rows padded to 80 B (=5x16, cp.async-legal,
//   stride 20 u32 -> conflict-free: r*20 mod 32 = {0,20,8,28,16,4,24,12}).
//   A hi/lo: 128 x 80 = 10240 B ; B hi/lo: 96 x 80 = 7680 B.
//   Buffer = 35840 B, double = 71680 B/CTA, x2 CTAs = 143.4 KB/SM.
// Pipeline: issue fill(c+1, nxt) -> MMA(cur) -> wait -> sync (1 sync/chunk).
// ---------------------------------------------------------------------------
#define A_HI 0
#define A_LO 10240
#define B_HI 20480
#define B_LO 28160
#define SM_BUF 35840
#define SM_TOTAL 71680
#define RSTR 20   // row stride in u32
#define RSTRB 80  // row stride in bytes

template <int KTOT, int XK>
__global__ void __launch_bounds__(256, 2)
gru_layer_mma(const __nv_bfloat16* __restrict__ xhi,
              const __nv_bfloat16* __restrict__ xlo,
              const __nv_bfloat16* __restrict__ hhi,
              const __nv_bfloat16* __restrict__ hlo,
              const float* __restrict__ hin,
              float* __restrict__ hout,
              u32* __restrict__ houthi,
              u32* __restrict__ houtlo,
              const __nv_bfloat16* __restrict__ Whi,
              const __nv_bfloat16* __restrict__ Wlo,
              const float* __restrict__ b_ih,
              const float* __restrict__ b_hh)
{
    extern __shared__ char smem[];
    const u32 sb = smem_to_u32(smem);

    const int tid = threadIdx.x;
    const int wid = tid >> 5;
    const int lane = tid & 31;
    const int g_ = lane >> 2;
    const int q_ = lane & 3;
    const int wm = wid & 3;
    const int wn = wid >> 2;
    const int mt = blockIdx.x >> 4;
    const int hc = blockIdx.x & 15;
    const int m0 = mt * 128;
    const int hc0 = hc * 32;

    const int CH = KTOT / 32;
    const int XCH = XK / 32;

    float acc[4][2][2][4];
#pragma unroll
    for (int p = 0; p < 4; ++p)
#pragma unroll
        for (int a = 0; a < 2; ++a)
#pragma unroll
            for (int b = 0; b < 2; ++b)
#pragma unroll
                for (int cc = 0; cc < 4; ++cc) acc[p][a][b][cc] = 0.f;

    // ---- fill helper: chunk c into buffer buf ---------------------------
    auto issue_fill = [&](int c, int buf) {
        const u32 base = sb + buf * SM_BUF;
        const bool is_x = (c < XCH);
        const __nv_bfloat16* ahi = is_x ? xhi : hhi;
        const __nv_bfloat16* alo = is_x ? xlo : hlo;
        const int stride = is_x ? XK : 512;
        const int col0 = is_x ? c * 32 : (c - XCH) * 32;
        // A: 128 rows x 32 k -> 128 x 4 x 16B per image
#pragma unroll
        for (int i = 0; i < 2; ++i) {
            const int e = tid + 256 * i;
            const int m = e >> 2, q = e & 3;
            const long so = (long)(m0 + m) * stride + col0 + q * 8;
            const u32 doff = m * RSTRB + q * 16;
            cp16(base + A_HI + doff, ahi + so);
            cp16(base + A_LO + doff, alo + so);
        }
        // B: 96 rows x 32 k -> 96 x 4 x 16B per image (384 chunks)
        {
            const int e = tid;           // first 256
            const int brow = e >> 2, q = e & 3;
            const int gate = brow >> 5, n = brow & 31;
            const long so = (long)(gate * 512 + hc0 + n) * KTOT + c * 32 + q * 8;
            const u32 doff = brow * RSTRB + q * 16;
            cp16(base + B_HI + doff, Whi + so);
            cp16(base + B_LO + doff, Wlo + so);
        }
        if (tid < 128) {                 // remaining 128
            const int e = tid + 256;
            const int brow = e >> 2, q = e & 3;
            const int gate = brow >> 5, n = brow & 31;
            const long so = (long)(gate * 512 + hc0 + n) * KTOT + c * 32 + q * 8;
            const u32 doff = brow * RSTRB + q * 16;
            cp16(base + B_HI + doff, Whi + so);
            cp16(base + B_LO + doff, Wlo + so);
        }
    };

    // ---- prologue -------------------------------------------------------
    issue_fill(0, 0);
    CP_COMMIT();
    CP_WAIT0();
    __syncthreads();

    // ---- pipelined chunk loop ------------------------------------------
#pragma unroll 1
    for (int c = 0; c < CH; ++c) {
        const int cur = c & 1;
        const bool more = (c + 1 < CH);
        if (more) {
            issue_fill(c + 1, cur ^ 1);
            CP_COMMIT();
        }

        // ---- MMA burst on current buffer --------------------------------
        {
            const u32* AHIp = (const u32*)(smem + cur * SM_BUF + A_HI);
            const u32* ALOp = (const u32*)(smem + cur * SM_BUF + A_LO);
            const u32* BHIp = (const u32*)(smem + cur * SM_BUF + B_HI);
            const u32* BLOp = (const u32*)(smem + cur * SM_BUF + B_LO);
            const bool is_x = (c < XCH);
            const int nplane = is_x ? 2 : 3;
#pragma unroll
            for (int ks = 0; ks < 2; ++ks) {
                const int k0 = ks * 8 + q_;
#pragma unroll
                for (int mtl = 0; mtl < 2; ++mtl) {
                    const int r0 = wm * 32 + mtl * 16 + g_;
                    u32 a_hi[4], a_lo[4];
                    a_hi[0] = AHIp[r0 * RSTR + k0];
                    a_hi[1] = AHIp[(r0 + 8) * RSTR + k0];
                    a_hi[2] = AHIp[r0 * RSTR + k0 + 4];
                    a_hi[3] = AHIp[(r0 + 8) * RSTR + k0 + 4];
                    a_lo[0] = ALOp[r0 * RSTR + k0];
                    a_lo[1] = ALOp[(r0 + 8) * RSTR + k0];
                    a_lo[2] = ALOp[r0 * RSTR + k0 + 4];
                    a_lo[3] = ALOp[(r0 + 8) * RSTR + k0 + 4];
#pragma unroll
                    for (int pl = 0; pl < 3; ++pl) {
                        const int gate = (pl == 2) ? 2 : pl;
                        const int ai = (pl == 2) ? nplane : pl;
#pragma unroll
                        for (int nt = 0; nt < 2; ++nt) {
                            const int br = gate * 32 + wn * 16 + nt * 8 + g_;
                            const u32 bh0 = BHIp[br * RSTR + k0];
                            const u32 bh1 = BHIp[br * RSTR + k0 + 4];
                            const u32 bl0 = BLOp[br * RSTR + k0];
                            const u32 bl1 = BLOp[br * RSTR + k0 + 4];
                            mma_bf16(acc[ai][mtl][nt], a_hi, bh0, bh1);
                            mma_bf16(acc[ai][mtl][nt], a_hi, bl0, bl1);
                            mma_bf16(acc[ai][mtl][nt], a_lo, bh0, bh1);
                        }
                    }
                }
            }
        }

        if (more) CP_WAIT0();
        __syncthreads();
    }

    // ---- epilogue: gate math + h write (f32 + split images) --------------
#pragma unroll
    for (int nt = 0; nt < 2; ++nt) {
        const int j = hc0 + wn * 16 + nt * 8 + 2 * q_;
        const float2 bir = *(const float2*)&b_ih[j];
        const float2 bhr = *(const float2*)&b_hh[j];
        const float2 biz = *(const float2*)&b_ih[512 + j];
        const float2 bhz = *(const float2*)&b_hh[512 + j];
        const float2 bin = *(const float2*)&b_ih[1024 + j];
        const float2 bhn = *(const float2*)&b_hh[1024 + j];
        const float brx = bir.x + bhr.x, bry = bir.y + bhr.y;
        const float bzx = biz.x + bhz.x, bzy = biz.y + bhz.y;
#pragma unroll
        for (int mtl = 0; mtl < 2; ++mtl) {
            const int ra = m0 + wm * 32 + mtl * 16 + g_;
#pragma unroll
            for (int rr = 0; rr < 2; ++rr) {
                const int row = ra + rr * 8;
                const float2 hold = *(const float2*)&hin[row * 512 + j];
                const float r0 = sigf(acc[0][mtl][nt][2 * rr] + brx);
                const float r1 = sigf(acc[0][mtl][nt][2 * rr + 1] + bry);
                const float z0 = sigf(acc[1][mtl][nt][2 * rr] + bzx);
                const float z1 = sigf(acc[1][mtl][nt][2 * rr + 1] + bzy);
                const float n0 = tanh_f(acc[2][mtl][nt][2 * rr] + bin.x
                                        + r0 * (acc[3][mtl][nt][2 * rr] + bhn.x));
                const float n1 = tanh_f(acc[2][mtl][nt][2 * rr + 1] + bin.y
                                        + r1 * (acc[3][mtl][nt][2 * rr + 1] + bhn.y));
                float2 o;
                o.x = n0 + z0 * (hold.x - n0);
                o.y = n1 + z1 * (hold.y - n1);
                *(float2*)&hout[row * 512 + j] = o;
                __nv_bfloat16 hx = __float2bfloat16_rn(o.x);
                __nv_bfloat16 hy = __float2bfloat16_rn(o.y);
                const int pi = (row * 512 + j) >> 1;
                houthi[pi] = bfpack(o.x, o.y);
                houtlo[pi] = bfpack(o.x - __bfloat162float(hx),
                                    o.y - __bfloat162float(hy));
            }
        }
    }
}

// ---------------------------------------------------------------------------
// fc + projection (fp32 / FFMA2), one launch per step. grid 128 x 16 batches.
// ---------------------------------------------------------------------------
__global__ void __launch_bounds__(256, 1)
fc_proj(const float* __restrict__ h1,
        const float* __restrict__ b_fc, const float* __restrict__ b_pj,
        float* __restrict__ xfc,
        u32* __restrict__ xfchi, u32* __restrict__ xfclo,
        float* __restrict__ y, int t)
{
    __shared__ float sh1[16 * 512];
    __shared__ float sx[16 * 128];
    const int tid = threadIdx.x;
    const int gb0 = blockIdx.x * 16;

    for (int i = tid; i < 8192; i += 256) sh1[i] = h1[gb0 * 512 + i];
    __syncthreads();

    {
        const int ox = tid & 31;
        const int bb = 2 * (tid >> 5);
        u64 acc[2][2] = {{0ull, 0ull}, {0ull, 0ull}};
        const float4* __restrict__ W4 = (const float4*)g_Wfc_t; // [512][32]
#pragma unroll 2
        for (int k = 0; k < Hh; k += 4) {
            F4 hv0, hv1;
            hv0.v = *(const float4*)&sh1[bb * Hh + k];
            hv1.v = *(const float4*)&sh1[(bb + 1) * Hh + k];
#pragma unroll
            for (int kk = 0; kk < 4; ++kk) {
                F4 w; w.v = __ldg(&W4[(k + kk) * 32 + ox]);
                const u64 h0p = pack2(hv0.f[kk]);
                const u64 h1p = pack2(hv1.f[kk]);
                ffma2(acc[0][0], h0p, w.d[0]);
                ffma2(acc[0][1], h0p, w.d[1]);
                ffma2(acc[1][0], h1p, w.d[0]);
                ffma2(acc[1][1], h1p, w.d[1]);
            }
        }
        F4 bf; bf.v = __ldg(((const float4*)b_fc) + ox);
        F4 o0, o1;
#pragma unroll
        for (int p = 0; p < 2; ++p) {
            const float2 a0 = unpack2(acc[0][p]);
            const float2 a1 = unpack2(acc[1][p]);
            o0.f[2 * p] = a0.x + bf.f[2 * p];
            o0.f[2 * p + 1] = a0.y + bf.f[2 * p + 1];
            o1.f[2 * p] = a1.x + bf.f[2 * p];
            o1.f[2 * p + 1] = a1.y + bf.f[2 * p + 1];
        }
        *(float4*)&sx[bb * DIN + 4 * ox]       = o0.v;
        *(float4*)&sx[(bb + 1) * DIN + 4 * ox] = o1.v;
    }
    __syncthreads();

    {
        const int bb = tid >> 4;
        const int ox = tid & 15;
        F4 acc; acc.v = __ldg(((const float4*)b_pj) + ox);
        const float4* __restrict__ W4 = (const float4*)g_Wpj_t; // [128][16]
#pragma unroll 2
        for (int d = 0; d < DIN; d += 4) {
            F4 xv; xv.v = *(const float4*)&sx[bb * DIN + d];
#pragma unroll
            for (int kk = 0; kk < 4; ++kk) {
                F4 w; w.v = __ldg(&W4[(d + kk) * 16 + ox]);
#pragma unroll
                for (int l = 0; l < 4; ++l)
                    acc.f[l] = fmaf(xv.f[kk], w.f[l], acc.f[l]);
            }
        }
        const size_t base = ((size_t)(gb0 + bb) * DOUT + 4 * ox) * TT + t;
        y[base]          = acc.f[0];
        y[base + TT]     = acc.f[1];
        y[base + 2 * TT] = acc.f[2];
        y[base + 3 * TT] = acc.f[3];
    }
    // xfc writeback: f32 + split bf16 images
    for (int i = tid; i < 1024; i += 256) {
        float2 v = *(float2*)&sx[2 * i];
        *(float2*)&xfc[gb0 * DIN + 2 * i] = v;
        __nv_bfloat16 hx = __float2bfloat16_rn(v.x);
        __nv_bfloat16 hy = __float2bfloat16_rn(v.y);
        xfchi[gb0 * 64 + i] = bfpack(v.x, v.y);
        xfclo[gb0 * 64 + i] = bfpack(v.x - __bfloat162float(hx),
                                     v.y - __bfloat162float(hy));
    }
}

// ---------------------------------------------------------------------------
// Entry point: 2 reorg + 96 x (layer0, layer1, fc_proj)
// ---------------------------------------------------------------------------
extern "C" void kernel_launch(void* const* d_in, const int* in_sizes, int n_in,
                              void* d_out, int out_size)
{
    (void)in_sizes; (void)n_in; (void)out_size;

    const float* x    = (const float*)d_in[0];
    const float* Wih0 = (const float*)d_in[1];
    const float* Whh0 = (const float*)d_in[2];
    const float* bih0 = (const float*)d_in[3];
    const float* bhh0 = (const float*)d_in[4];
    const float* Wih1 = (const float*)d_in[5];
    const float* Whh1 = (const float*)d_in[6];
    const float* bih1 = (const float*)d_in[7];
    const float* bhh1 = (const float*)d_in[8];
    const float* Wfc  = (const float*)d_in[9];
    const float* bfc  = (const float*)d_in[10];
    const float* Wpj  = (const float*)d_in[11];
    const float* bpj  = (const float*)d_in[12];
    float* y = (float*)d_out;

    float *h0a, *h0b, *h1a, *h1b, *xf;
    __nv_bfloat16 *W0hi, *W0lo, *W1hi, *W1lo;
    __nv_bfloat16 *h0hiA, *h0loA, *h0hiB, *h0loB;
    __nv_bfloat16 *h1hiA, *h1loA, *h1hiB, *h1loB;
    __nv_bfloat16 *xfhi, *xflo;
    cudaGetSymbolAddress((void**)&h0a, g_h0a);
    cudaGetSymbolAddress((void**)&h0b, g_h0b);
    cudaGetSymbolAddress((void**)&h1a, g_h1a);
    cudaGetSymbolAddress((void**)&h1b, g_h1b);
    cudaGetSymbolAddress((void**)&xf,  g_xfc);
    cudaGetSymbolAddress((void**)&W0hi, g_W0hi);
    cudaGetSymbolAddress((void**)&W0lo, g_W0lo);
    cudaGetSymbolAddress((void**)&W1hi, g_W1hi);
    cudaGetSymbolAddress((void**)&W1lo, g_W1lo);
    cudaGetSymbolAddress((void**)&h0hiA, g_h0hi_a);
    cudaGetSymbolAddress((void**)&h0loA, g_h0lo_a);
    cudaGetSymbolAddress((void**)&h0hiB, g_h0hi_b);
    cudaGetSymbolAddress((void**)&h0loB, g_h0lo_b);
    cudaGetSymbolAddress((void**)&h1hiA, g_h1hi_a);
    cudaGetSymbolAddress((void**)&h1loA, g_h1lo_a);
    cudaGetSymbolAddress((void**)&h1hiB, g_h1hi_b);
    cudaGetSymbolAddress((void**)&h1loB, g_h1lo_b);
    cudaGetSymbolAddress((void**)&xfhi, g_xfchi);
    cudaGetSymbolAddress((void**)&xflo, g_xfclo);

    cudaFuncSetAttribute(gru_layer_mma<K0TOT, DIN>,
                         cudaFuncAttributeMaxDynamicSharedMemorySize, SM_TOTAL);
    cudaFuncSetAttribute(gru_layer_mma<K1TOT, 512>,
                         cudaFuncAttributeMaxDynamicSharedMemorySize, SM_TOTAL);

    {
        const int total = 3 * 512 * K0TOT + 3 * 512 * K1TOT;
        pack_weights<<<(total + 255) / 256, 256>>>(Wih0, Whh0, Wih1, Whh1);
    }
    {
        const int total = Hh * DIN + DIN * DOUT + Bsz * Hh + Bsz * DIN;
        reorg_fc_init<<<(total + 255) / 256, 256>>>(Wfc, Wpj, x);
    }

    for (int t = 0; t < TT; ++t) {
        const int ping = t & 1;
        const float* h0in = ping ? h0b : h0a;
        float*       h0out = ping ? h0a : h0b;
        const float* h1in = ping ? h1b : h1a;
        float*       h1out = ping ? h1a : h1b;
        const __nv_bfloat16* h0hi_in = ping ? h0hiB : h0hiA;
        const __nv_bfloat16* h0lo_in = ping ? h0loB : h0loA;
        __nv_bfloat16* h0hi_out = ping ? h0hiA : h0hiB;
        __nv_bfloat16* h0lo_out = ping ? h0loA : h0loB;
        const __nv_bfloat16* h1hi_in = ping ? h1hiB : h1hiA;
        const __nv_bfloat16* h1lo_in = ping ? h1loB : h1loA;
        __nv_bfloat16* h1hi_out = ping ? h1hiA : h1hiB;
        __nv_bfloat16* h1lo_out = ping ? h1loA : h1loB;

        gru_layer_mma<K0TOT, DIN><<<256, 256, SM_TOTAL>>>(
            xfhi, xflo, h0hi_in, h0lo_in, h0in,
            h0out, (u32*)h0hi_out, (u32*)h0lo_out,
            W0hi, W0lo, bih0, bhh0);
        gru_layer_mma<K1TOT, 512><<<256, 256, SM_TOTAL>>>(
            h0hi_out, h0lo_out, h1hi_in, h1lo_in, h1in,
            h1out, (u32*)h1hi_out, (u32*)h1lo_out,
            W1hi, W1lo, bih1, bhh1);
        fc_proj<<<128, 256>>>(h1out, bfc, bpj, xf,
                              (u32*)xfhi, (u32*)xflo, y, t);
    }
}